// round 8
// baseline (speedup 1.0000x reference)
#include <cuda_runtime.h>
#include <cuda_fp16.h>
#include <cstdint>

// ---------------------------------------------------------------------------
// FPN head via legacy tensor cores (mma.sync m16n8k16 f16, fp32 accum).
// R8: double-buffered B smem staging overlapped with the MMA stream (stage
// chunk cc+1 before running MMAs of chunk cc), float4-vectorized interior
// staging (block tile spans full image width -> w-halo is always zero).
// A (weights) in fragment-direct gmem layout via LDG.128. 1 barrier/chunk.
// Output: [64, 240] fp32  (c1:128 | c2:64 | c3:32 | c4:16)
// ---------------------------------------------------------------------------

typedef unsigned int u32;

// A fragment image: [l][gi(36)][rg(8)][ks(2)][lane(32)] x uint4
__device__ uint4 g_wA[3 * 36 * 8 * 2 * 32];

// ---- PTX helpers ----------------------------------------------------------
__device__ __forceinline__ u32 smem_u32(const void* p) {
    u32 a;
    asm("{ .reg .u64 t; cvta.to.shared.u64 t, %1; cvt.u32.u64 %0, t; }"
        : "=r"(a) : "l"(p));
    return a;
}
__device__ __forceinline__ void ldm_x4(u32* r, u32 addr) {
    asm volatile("ldmatrix.sync.aligned.m8n8.x4.shared.b16 {%0,%1,%2,%3}, [%4];"
                 : "=r"(r[0]), "=r"(r[1]), "=r"(r[2]), "=r"(r[3]) : "r"(addr));
}
__device__ __forceinline__ void mma16816(float* d, const uint4 a, u32 b0, u32 b1) {
    asm volatile(
        "mma.sync.aligned.m16n8k16.row.col.f32.f16.f16.f32 "
        "{%0,%1,%2,%3}, {%4,%5,%6,%7}, {%8,%9}, {%0,%1,%2,%3};"
        : "+f"(d[0]), "+f"(d[1]), "+f"(d[2]), "+f"(d[3])
        : "r"(a.x), "r"(a.y), "r"(a.z), "r"(a.w), "r"(b0), "r"(b1));
}

// ---- weight prep: w[o][c][tap] fp32 -> A fragment image -------------------
__global__ void prep_wA_kernel(const float* __restrict__ w1,
                               const float* __restrict__ w2,
                               const float* __restrict__ w3) {
    int i = blockIdx.x * 256 + threadIdx.x;          // one u32 each
    if (i >= 3 * 36 * 2048) return;
    int q    = i & 3;
    int lane = (i >> 2) & 31;
    int ks   = (i >> 7) & 1;
    int rg   = (i >> 8) & 7;
    int gi   = (i >> 11) % 36;
    int l    = i / (36 << 11);
    const float* src = (l == 0) ? w1 : (l == 1) ? w2 : w3;
    int o = rg * 16 + (lane >> 2) + (q & 1) * 8;
    int k = ks * 16 + (lane & 3) * 2 + (q >> 1) * 8;
    int c = (gi / 9) * 32 + k;
    int tap = gi % 9;
    __half2 hv = __floats2half2_rn(src[o * 1152 + c * 9 + tap],
                                   src[o * 1152 + (c + 1) * 9 + tap]);
    ((u32*)g_wA)[i] = *(u32*)&hv;
}

// ---- out init: bpl bias for c1..c3 regions --------------------------------
__global__ void init_out_kernel(const float* __restrict__ bpl1,
                                const float* __restrict__ bpl2,
                                const float* __restrict__ bpl3,
                                float* __restrict__ out) {
    int i = blockIdx.x * blockDim.x + threadIdx.x;
    if (i >= 64 * 224) return;
    int j = i % 224;
    out[(i / 224) * 240 + j] = (j < 128) ? bpl1[0] : (j < 192) ? bpl2[0] : bpl3[0];
}

// ---- fused HMMA conv + epilogue -------------------------------------------
// Block: 512 threads = 16 warps as 2(m) x 8(n). Warp tile: 64 o x 32 n.
// Block tile: 128 o x 256 n = R rows x W cols (full image width).
// SMEM: sCol(256f)@0, B double buffer @1024:
//   [(R+2)*(W+2) pos][40 f16] n-major, 16B-block XOR swizzle.
template <int H, int W, int LW, int R, int BASE>
__global__ void __launch_bounds__(512, 1)
conv_mma_kernel(const float* __restrict__ x,      // [64,128,H,W]
                const uint4* __restrict__ wA,     // level slice of g_wA
                const float* __restrict__ bs,     // [128]
                const float* __restrict__ wt,     // [128]
                const float* __restrict__ bt,     // [1]
                const float* __restrict__ wpl,    // [H]
                float* __restrict__ out) {
    constexpr int NW = W + 2;
    constexpr int NP = (R + 2) * NW;
    constexpr int B_OFF = 1024;
    constexpr int BBYTES = NP * 80;
    constexpr int W4 = W / 4;

    extern __shared__ char smem[];
    float* sCol = (float*)smem;
    const u32 smu = smem_u32(smem);

    const int tid = threadIdx.x;
    const int warp = tid >> 5;
    const int lane = tid & 31;
    const int warpm = warp & 1;
    const int warpn = warp >> 1;   // 0..7, each 32 n

    const int TPH = H / R;
    const int b = blockIdx.x / TPH;
    const int h0 = (blockIdx.x % TPH) * R;
    const float* xb = x + (size_t)b * 128 * H * W;

    if (tid < 256) sCol[tid] = 0.f;

    // hoisted B-tile geometry (njp group 0 and 1)
    int p0[2];
#pragma unroll
    for (int j = 0; j < 2; j++) {
        int ng = warpn * 32 + j * 16 + (lane >> 4) * 8;
        int trow = ng >> LW;
        int tcol = ng & (W - 1);
        p0[j] = trow * NW + tcol + (lane & 7);
    }
    const int kbh = (lane >> 3) & 1;

    float d[4][4][4];
#pragma unroll
    for (int mi = 0; mi < 4; mi++)
#pragma unroll
        for (int nj = 0; nj < 4; nj++)
#pragma unroll
            for (int q = 0; q < 4; q++) d[mi][nj][q] = 0.f;

    // ---- staging helper (lambda-style macro via inline code) --------------
    // halo columns (w=-1, w=W) are outside the full-width image -> zero.
#define STAGE_B(ccv, bufv)                                                   \
    do {                                                                     \
        char* dstc = smem + B_OFF + (bufv) * BBYTES;                         \
        const int c0ch = (ccv) * 32;                                         \
        for (int idx = tid; idx < 16 * (R + 2) * 2; idx += 512) {            \
            int cp = idx / ((R + 2) * 2);                                    \
            int rem = idx - cp * ((R + 2) * 2);                              \
            int r = rem >> 1;                                                \
            int p = r * NW + (rem & 1) * (NW - 1);                           \
            int word = p * 20 + ((((cp >> 2) ^ (p & 3)) << 2)) + (cp & 3);   \
            *(u32*)(dstc + word * 4) = 0u;                                   \
        }                                                                    \
        for (int idx = tid; idx < 16 * (R + 2) * W4; idx += 512) {           \
            int cp = idx / ((R + 2) * W4);                                   \
            int rem = idx - cp * ((R + 2) * W4);                             \
            int r = rem / W4;                                                \
            int w4 = (rem - r * W4) * 4;                                     \
            int hin = h0 + r - 1;                                            \
            float4 v0 = {0.f, 0.f, 0.f, 0.f}, v1 = v0;                       \
            if (hin >= 0 && hin < H) {                                       \
                const float* bp =                                            \
                    xb + ((size_t)(c0ch + 2 * cp) * H + hin) * W + w4;       \
                v0 = *(const float4*)bp;                                     \
                v1 = *(const float4*)(bp + H * W);                           \
            }                                                                \
            const float* f0 = (const float*)&v0;                            \
            const float* f1 = (const float*)&v1;                            \
            _Pragma("unroll")                                                \
            for (int dw = 0; dw < 4; dw++) {                                 \
                int p = r * NW + w4 + dw + 1;                                \
                __half2 hv = __floats2half2_rn(f0[dw], f1[dw]);              \
                int word = p * 20 + ((((cp >> 2) ^ (p & 3)) << 2)) + (cp & 3);\
                *(__half2*)(dstc + word * 4) = hv;                           \
            }                                                                \
        }                                                                    \
    } while (0)

    STAGE_B(0, 0);
    __syncthreads();

    for (int cc = 0; cc < 4; cc++) {
        // overlap: stage next chunk into the other buffer before MMAs
        if (cc < 3) STAGE_B(cc + 1, (cc + 1) & 1);

        const u32 bbase = smu + B_OFF + (cc & 1) * BBYTES;
        // 9 taps, straight-line: A via LDG.128, B via ldmatrix
#pragma unroll
        for (int tap = 0; tap < 9; tap++) {
            const int gi = cc * 9 + tap;
            const int dy = tap / 3;
            const int dx = tap - dy * 3;
            const int pofs = dy * NW + dx;
#pragma unroll
            for (int ks = 0; ks < 2; ks++) {
                uint4 a[4];
#pragma unroll
                for (int mi = 0; mi < 4; mi++) {
                    int rg = warpm * 4 + mi;
                    a[mi] = wA[((gi * 8 + rg) * 2 + ks) * 32 + lane];
                }
                const int kb = ks * 2 + kbh;
#pragma unroll
                for (int j = 0; j < 2; j++) {
                    int p = p0[j] + pofs;
                    u32 bf[4];
                    ldm_x4(bf, bbase + p * 80 + ((kb ^ (p & 3)) << 4));
#pragma unroll
                    for (int mi = 0; mi < 4; mi++) {
                        mma16816(d[mi][2 * j], a[mi], bf[0], bf[1]);
                        mma16816(d[mi][2 * j + 1], a[mi], bf[2], bf[3]);
                    }
                }
            }
        }
        __syncthreads();
    }

    // ---- epilogue: bias + ReLU + dot(w_t), reduce, pool -------------------
    const int g = lane >> 2;
    const int tid4 = lane & 3;
    float bsv[4][2], wtv[4][2];
#pragma unroll
    for (int mi = 0; mi < 4; mi++)
#pragma unroll
        for (int hh = 0; hh < 2; hh++) {
            int o = warpm * 64 + mi * 16 + hh * 8 + g;
            bsv[mi][hh] = bs[o];
            wtv[mi][hh] = wt[o];
        }
#pragma unroll
    for (int nj = 0; nj < 4; nj++) {
        float v0 = 0.f, v1 = 0.f;
#pragma unroll
        for (int mi = 0; mi < 4; mi++) {
            v0 += fmaxf(d[mi][nj][0] + bsv[mi][0], 0.f) * wtv[mi][0]
                + fmaxf(d[mi][nj][2] + bsv[mi][1], 0.f) * wtv[mi][1];
            v1 += fmaxf(d[mi][nj][1] + bsv[mi][0], 0.f) * wtv[mi][0]
                + fmaxf(d[mi][nj][3] + bsv[mi][1], 0.f) * wtv[mi][1];
        }
        v0 += __shfl_xor_sync(0xffffffffu, v0, 4);
        v0 += __shfl_xor_sync(0xffffffffu, v0, 8);
        v0 += __shfl_xor_sync(0xffffffffu, v0, 16);
        v1 += __shfl_xor_sync(0xffffffffu, v1, 4);
        v1 += __shfl_xor_sync(0xffffffffu, v1, 8);
        v1 += __shfl_xor_sync(0xffffffffu, v1, 16);
        if (lane < 4) {
            int n = warpn * 32 + nj * 8 + tid4 * 2;
            atomicAdd(&sCol[n], v0);
            atomicAdd(&sCol[n + 1], v1);
        }
    }
    __syncthreads();

    if (tid < W) {
        const float btv = bt[0];
        float s = 0.f;
#pragma unroll
        for (int r = 0; r < R; r++)
            s += wpl[h0 + r] * (sCol[r * W + tid] + btv);
        atomicAdd(&out[b * 240 + BASE + tid], s);
    }
}

// ---- p5 path: tidy 1x1 (512->1) + pool over h=8, memory bound -------------
__global__ void p5_kernel(const float* __restrict__ p5,
                          const float* __restrict__ wt,   // [512]
                          const float* __restrict__ bt,   // [1]
                          const float* __restrict__ wpl,  // [8]
                          const float* __restrict__ bpl,  // [1]
                          float* __restrict__ out) {
    const int b = blockIdx.x;
    const int tid = threadIdx.x;
    const int w = tid & 15;
    const int g = tid >> 4;
    __shared__ float red[256];
    __shared__ float spl[8];
    if (tid < 8) spl[tid] = wpl[tid];
    __syncthreads();

    const float* pb = p5 + (size_t)b * 512 * 8 * 16;
    float accv = 0.f;
    for (int c = g; c < 512; c += 16) {
        float wc = wt[c];
        const float* row = pb + (size_t)c * 8 * 16 + w;
#pragma unroll
        for (int h = 0; h < 8; h++)
            accv = fmaf(wc * spl[h], row[h * 16], accv);
    }
    red[tid] = accv;
    __syncthreads();
    if (tid < 16) {
        float s = 0.f;
#pragma unroll
        for (int gg = 0; gg < 16; gg++) s += red[gg * 16 + tid];
        float sumpl = 0.f;
#pragma unroll
        for (int h = 0; h < 8; h++) sumpl += spl[h];
        out[b * 240 + 224 + tid] = s + bt[0] * sumpl + bpl[0];
    }
}

// ---------------------------------------------------------------------------
extern "C" void kernel_launch(void* const* d_in, const int* in_sizes, int n_in,
                              void* d_out, int out_size) {
    const float* p2 = (const float*)d_in[0];
    const float* p3 = (const float*)d_in[1];
    const float* p4 = (const float*)d_in[2];
    const float* p5 = (const float*)d_in[3];
    const float* w_s1 = (const float*)d_in[4];
    const float* b_s1 = (const float*)d_in[5];
    const float* w_s2 = (const float*)d_in[6];
    const float* b_s2 = (const float*)d_in[7];
    const float* w_s3 = (const float*)d_in[8];
    const float* b_s3 = (const float*)d_in[9];
    const float* w_t1 = (const float*)d_in[10];
    const float* b_t1 = (const float*)d_in[11];
    const float* w_t2 = (const float*)d_in[12];
    const float* b_t2 = (const float*)d_in[13];
    const float* w_t3 = (const float*)d_in[14];
    const float* b_t3 = (const float*)d_in[15];
    const float* w_t4 = (const float*)d_in[16];
    const float* b_t4 = (const float*)d_in[17];
    const float* w_pl1 = (const float*)d_in[18];
    const float* b_pl1 = (const float*)d_in[19];
    const float* w_pl2 = (const float*)d_in[20];
    const float* b_pl2 = (const float*)d_in[21];
    const float* w_pl3 = (const float*)d_in[22];
    const float* b_pl3 = (const float*)d_in[23];
    const float* w_pl4 = (const float*)d_in[24];
    const float* b_pl4 = (const float*)d_in[25];
    float* out = (float*)d_out;

    prep_wA_kernel<<<(3 * 36 * 2048 + 255) / 256, 256>>>(w_s1, w_s2, w_s3);
    init_out_kernel<<<(64 * 224 + 255) / 256, 256>>>(b_pl1, b_pl2, b_pl3, out);

    uint4* wAd;
    cudaGetSymbolAddress((void**)&wAd, g_wA);

    // dynamic smem: 1024 + 2 * NP*80 bytes
    const int sm1 = 1024 + 2 * (2 + 2) * 130 * 80;  // 84224
    const int sm2 = 1024 + 2 * (4 + 2) * 66 * 80;   // 64384
    const int sm3 = 1024 + 2 * (8 + 2) * 34 * 80;   // 55424
    cudaFuncSetAttribute(conv_mma_kernel<64, 128, 7, 2, 0>,
                         cudaFuncAttributeMaxDynamicSharedMemorySize, sm1);
    cudaFuncSetAttribute(conv_mma_kernel<32, 64, 6, 4, 128>,
                         cudaFuncAttributeMaxDynamicSharedMemorySize, sm2);
    cudaFuncSetAttribute(conv_mma_kernel<16, 32, 5, 8, 192>,
                         cudaFuncAttributeMaxDynamicSharedMemorySize, sm3);

    conv_mma_kernel<64, 128, 7, 2, 0><<<64 * 32, 512, sm1>>>(
        p2, wAd + 0 * 36 * 512, b_s1, w_t1, b_t1, w_pl1, out);
    conv_mma_kernel<32, 64, 6, 4, 128><<<64 * 8, 512, sm2>>>(
        p3, wAd + 1 * 36 * 512, b_s2, w_t2, b_t2, w_pl2, out);
    conv_mma_kernel<16, 32, 5, 8, 192><<<64 * 2, 512, sm3>>>(
        p4, wAd + 2 * 36 * 512, b_s3, w_t3, b_t3, w_pl3, out);
    p5_kernel<<<64, 256>>>(p5, w_t4, b_t4, w_pl4, b_pl4, out);
}

// round 9
// speedup vs baseline: 1.0430x; 1.0430x over previous
#include <cuda_runtime.h>
#include <cuda_fp16.h>
#include <cstdint>

// ---------------------------------------------------------------------------
// FPN head via legacy tensor cores (mma.sync m16n8k16 f16, fp32 accum).
// R9: warp tile 64o x 64n (mi=4, nj=8) @ 8 warps -> 1.0 L1-wavefront per MMA
// (was 1.5). A fragment-direct via LDG.128, B double-buffered stage-ahead,
// float4 staging, 1 barrier per 32-ch chunk. Fused epilogue.
// Output: [64, 240] fp32  (c1:128 | c2:64 | c3:32 | c4:16)
// ---------------------------------------------------------------------------

typedef unsigned int u32;

// A fragment image: [l][gi(36)][rg(8)][ks(2)][lane(32)] x uint4
__device__ uint4 g_wA[3 * 36 * 8 * 2 * 32];

// ---- PTX helpers ----------------------------------------------------------
__device__ __forceinline__ u32 smem_u32(const void* p) {
    u32 a;
    asm("{ .reg .u64 t; cvta.to.shared.u64 t, %1; cvt.u32.u64 %0, t; }"
        : "=r"(a) : "l"(p));
    return a;
}
__device__ __forceinline__ void ldm_x4(u32* r, u32 addr) {
    asm volatile("ldmatrix.sync.aligned.m8n8.x4.shared.b16 {%0,%1,%2,%3}, [%4];"
                 : "=r"(r[0]), "=r"(r[1]), "=r"(r[2]), "=r"(r[3]) : "r"(addr));
}
__device__ __forceinline__ void mma16816(float* d, const uint4 a, u32 b0, u32 b1) {
    asm volatile(
        "mma.sync.aligned.m16n8k16.row.col.f32.f16.f16.f32 "
        "{%0,%1,%2,%3}, {%4,%5,%6,%7}, {%8,%9}, {%0,%1,%2,%3};"
        : "+f"(d[0]), "+f"(d[1]), "+f"(d[2]), "+f"(d[3])
        : "r"(a.x), "r"(a.y), "r"(a.z), "r"(a.w), "r"(b0), "r"(b1));
}

// ---- weight prep: w[o][c][tap] fp32 -> A fragment image -------------------
__global__ void prep_wA_kernel(const float* __restrict__ w1,
                               const float* __restrict__ w2,
                               const float* __restrict__ w3) {
    int i = blockIdx.x * 256 + threadIdx.x;          // one u32 each
    if (i >= 3 * 36 * 2048) return;
    int q    = i & 3;
    int lane = (i >> 2) & 31;
    int ks   = (i >> 7) & 1;
    int rg   = (i >> 8) & 7;
    int gi   = (i >> 11) % 36;
    int l    = i / (36 << 11);
    const float* src = (l == 0) ? w1 : (l == 1) ? w2 : w3;
    int o = rg * 16 + (lane >> 2) + (q & 1) * 8;
    int k = ks * 16 + (lane & 3) * 2 + (q >> 1) * 8;
    int c = (gi / 9) * 32 + k;
    int tap = gi % 9;
    __half2 hv = __floats2half2_rn(src[o * 1152 + c * 9 + tap],
                                   src[o * 1152 + (c + 1) * 9 + tap]);
    ((u32*)g_wA)[i] = *(u32*)&hv;
}

// ---- out init: bpl bias for c1..c3 regions --------------------------------
__global__ void init_out_kernel(const float* __restrict__ bpl1,
                                const float* __restrict__ bpl2,
                                const float* __restrict__ bpl3,
                                float* __restrict__ out) {
    int i = blockIdx.x * blockDim.x + threadIdx.x;
    if (i >= 64 * 224) return;
    int j = i % 224;
    out[(i / 224) * 240 + j] = (j < 128) ? bpl1[0] : (j < 192) ? bpl2[0] : bpl3[0];
}

// ---- fused HMMA conv + epilogue -------------------------------------------
// Block: 256 threads = 8 warps as 2(m) x 4(n). Warp tile: 64 o x 64 n.
// Block tile: 128 o x 256 n = R rows x W cols (full image width).
// SMEM: sCol(256f)@0, B double buffer @1024:
//   [(R+2)*(W+2) pos][40 f16] n-major, 16B-block XOR swizzle.
template <int H, int W, int LW, int R, int BASE>
__global__ void __launch_bounds__(256, 1)
conv_mma_kernel(const float* __restrict__ x,      // [64,128,H,W]
                const uint4* __restrict__ wA,     // level slice of g_wA
                const float* __restrict__ bs,     // [128]
                const float* __restrict__ wt,     // [128]
                const float* __restrict__ bt,     // [1]
                const float* __restrict__ wpl,    // [H]
                float* __restrict__ out) {
    constexpr int NW = W + 2;
    constexpr int NP = (R + 2) * NW;
    constexpr int B_OFF = 1024;
    constexpr int BBYTES = NP * 80;
    constexpr int W4 = W / 4;

    extern __shared__ char smem[];
    float* sCol = (float*)smem;
    const u32 smu = smem_u32(smem);

    const int tid = threadIdx.x;
    const int warp = tid >> 5;
    const int lane = tid & 31;
    const int warpm = warp & 1;
    const int warpn = warp >> 1;   // 0..3, each 64 n

    const int TPH = H / R;
    const int b = blockIdx.x / TPH;
    const int h0 = (blockIdx.x % TPH) * R;
    const float* xb = x + (size_t)b * 128 * H * W;

    sCol[tid] = 0.f;

    // hoisted B-tile geometry (4 nj-pair groups)
    int p0[4];
#pragma unroll
    for (int j = 0; j < 4; j++) {
        int ng = warpn * 64 + j * 16 + (lane >> 4) * 8;
        int trow = ng >> LW;
        int tcol = ng & (W - 1);
        p0[j] = trow * NW + tcol + (lane & 7);
    }
    const int kbh = (lane >> 3) & 1;

    float d[4][8][4];
#pragma unroll
    for (int mi = 0; mi < 4; mi++)
#pragma unroll
        for (int nj = 0; nj < 8; nj++)
#pragma unroll
            for (int q = 0; q < 4; q++) d[mi][nj][q] = 0.f;

    // ---- staging: halo columns zero (tile spans full image width) ---------
#define STAGE_B(ccv, bufv)                                                   \
    do {                                                                     \
        char* dstc = smem + B_OFF + (bufv) * BBYTES;                         \
        const int c0ch = (ccv) * 32;                                         \
        for (int idx = tid; idx < 16 * (R + 2) * 2; idx += 256) {            \
            int cp = idx / ((R + 2) * 2);                                    \
            int rem = idx - cp * ((R + 2) * 2);                              \
            int r = rem >> 1;                                                \
            int p = r * NW + (rem & 1) * (NW - 1);                           \
            int word = p * 20 + ((((cp >> 2) ^ (p & 3)) << 2)) + (cp & 3);   \
            *(u32*)(dstc + word * 4) = 0u;                                   \
        }                                                                    \
        for (int idx = tid; idx < 16 * (R + 2) * W4; idx += 256) {           \
            int cp = idx / ((R + 2) * W4);                                   \
            int rem = idx - cp * ((R + 2) * W4);                             \
            int r = rem / W4;                                                \
            int w4 = (rem - r * W4) * 4;                                     \
            int hin = h0 + r - 1;                                            \
            float4 v0 = {0.f, 0.f, 0.f, 0.f}, v1 = v0;                       \
            if (hin >= 0 && hin < H) {                                       \
                const float* bp =                                            \
                    xb + ((size_t)(c0ch + 2 * cp) * H + hin) * W + w4;       \
                v0 = *(const float4*)bp;                                     \
                v1 = *(const float4*)(bp + H * W);                           \
            }                                                                \
            const float* f0 = (const float*)&v0;                            \
            const float* f1 = (const float*)&v1;                            \
            _Pragma("unroll")                                                \
            for (int dw = 0; dw < 4; dw++) {                                 \
                int p = r * NW + w4 + dw + 1;                                \
                __half2 hv = __floats2half2_rn(f0[dw], f1[dw]);              \
                int word = p * 20 + ((((cp >> 2) ^ (p & 3)) << 2)) + (cp & 3);\
                *(__half2*)(dstc + word * 4) = hv;                           \
            }                                                                \
        }                                                                    \
    } while (0)

    STAGE_B(0, 0);
    __syncthreads();

    for (int cc = 0; cc < 4; cc++) {
        // stage-ahead: next chunk into the other buffer before this MMA phase
        if (cc < 3) STAGE_B(cc + 1, (cc + 1) & 1);

        const u32 bbase = smu + B_OFF + (cc & 1) * BBYTES;
#pragma unroll
        for (int tap = 0; tap < 9; tap++) {
            const int gi = cc * 9 + tap;
            const int dy = tap / 3;
            const int dx = tap - dy * 3;
            const int pofs = dy * NW + dx;
#pragma unroll
            for (int ks = 0; ks < 2; ks++) {
                uint4 a[4];
#pragma unroll
                for (int mi = 0; mi < 4; mi++) {
                    int rg = warpm * 4 + mi;
                    a[mi] = wA[((gi * 8 + rg) * 2 + ks) * 32 + lane];
                }
                const int kb = ks * 2 + kbh;
#pragma unroll
                for (int j = 0; j < 4; j++) {
                    int p = p0[j] + pofs;
                    u32 bf[4];
                    ldm_x4(bf, bbase + p * 80 + ((kb ^ (p & 3)) << 4));
#pragma unroll
                    for (int mi = 0; mi < 4; mi++) {
                        mma16816(d[mi][2 * j], a[mi], bf[0], bf[1]);
                        mma16816(d[mi][2 * j + 1], a[mi], bf[2], bf[3]);
                    }
                }
            }
        }
        __syncthreads();
    }

    // ---- epilogue: bias + ReLU + dot(w_t), reduce, pool -------------------
    const int g = lane >> 2;
    const int tid4 = lane & 3;
    float bsv[4][2], wtv[4][2];
#pragma unroll
    for (int mi = 0; mi < 4; mi++)
#pragma unroll
        for (int hh = 0; hh < 2; hh++) {
            int o = warpm * 64 + mi * 16 + hh * 8 + g;
            bsv[mi][hh] = bs[o];
            wtv[mi][hh] = wt[o];
        }
#pragma unroll
    for (int nj = 0; nj < 8; nj++) {
        float v0 = 0.f, v1 = 0.f;
#pragma unroll
        for (int mi = 0; mi < 4; mi++) {
            v0 += fmaxf(d[mi][nj][0] + bsv[mi][0], 0.f) * wtv[mi][0]
                + fmaxf(d[mi][nj][2] + bsv[mi][1], 0.f) * wtv[mi][1];
            v1 += fmaxf(d[mi][nj][1] + bsv[mi][0], 0.f) * wtv[mi][0]
                + fmaxf(d[mi][nj][3] + bsv[mi][1], 0.f) * wtv[mi][1];
        }
        v0 += __shfl_xor_sync(0xffffffffu, v0, 4);
        v0 += __shfl_xor_sync(0xffffffffu, v0, 8);
        v0 += __shfl_xor_sync(0xffffffffu, v0, 16);
        v1 += __shfl_xor_sync(0xffffffffu, v1, 4);
        v1 += __shfl_xor_sync(0xffffffffu, v1, 8);
        v1 += __shfl_xor_sync(0xffffffffu, v1, 16);
        if (lane < 4) {
            int n = warpn * 64 + nj * 8 + tid4 * 2;
            atomicAdd(&sCol[n], v0);
            atomicAdd(&sCol[n + 1], v1);
        }
    }
    __syncthreads();

    if (tid < W) {
        const float btv = bt[0];
        float s = 0.f;
#pragma unroll
        for (int r = 0; r < R; r++)
            s += wpl[h0 + r] * (sCol[r * W + tid] + btv);
        atomicAdd(&out[b * 240 + BASE + tid], s);
    }
}

// ---- p5 path: tidy 1x1 (512->1) + pool over h=8, memory bound -------------
__global__ void p5_kernel(const float* __restrict__ p5,
                          const float* __restrict__ wt,   // [512]
                          const float* __restrict__ bt,   // [1]
                          const float* __restrict__ wpl,  // [8]
                          const float* __restrict__ bpl,  // [1]
                          float* __restrict__ out) {
    const int b = blockIdx.x;
    const int tid = threadIdx.x;
    const int w = tid & 15;
    const int g = tid >> 4;
    __shared__ float red[256];
    __shared__ float spl[8];
    if (tid < 8) spl[tid] = wpl[tid];
    __syncthreads();

    const float* pb = p5 + (size_t)b * 512 * 8 * 16;
    float accv = 0.f;
    for (int c = g; c < 512; c += 16) {
        float wc = wt[c];
        const float* row = pb + (size_t)c * 8 * 16 + w;
#pragma unroll
        for (int h = 0; h < 8; h++)
            accv = fmaf(wc * spl[h], row[h * 16], accv);
    }
    red[tid] = accv;
    __syncthreads();
    if (tid < 16) {
        float s = 0.f;
#pragma unroll
        for (int gg = 0; gg < 16; gg++) s += red[gg * 16 + tid];
        float sumpl = 0.f;
#pragma unroll
        for (int h = 0; h < 8; h++) sumpl += spl[h];
        out[b * 240 + 224 + tid] = s + bt[0] * sumpl + bpl[0];
    }
}

// ---------------------------------------------------------------------------
extern "C" void kernel_launch(void* const* d_in, const int* in_sizes, int n_in,
                              void* d_out, int out_size) {
    const float* p2 = (const float*)d_in[0];
    const float* p3 = (const float*)d_in[1];
    const float* p4 = (const float*)d_in[2];
    const float* p5 = (const float*)d_in[3];
    const float* w_s1 = (const float*)d_in[4];
    const float* b_s1 = (const float*)d_in[5];
    const float* w_s2 = (const float*)d_in[6];
    const float* b_s2 = (const float*)d_in[7];
    const float* w_s3 = (const float*)d_in[8];
    const float* b_s3 = (const float*)d_in[9];
    const float* w_t1 = (const float*)d_in[10];
    const float* b_t1 = (const float*)d_in[11];
    const float* w_t2 = (const float*)d_in[12];
    const float* b_t2 = (const float*)d_in[13];
    const float* w_t3 = (const float*)d_in[14];
    const float* b_t3 = (const float*)d_in[15];
    const float* w_t4 = (const float*)d_in[16];
    const float* b_t4 = (const float*)d_in[17];
    const float* w_pl1 = (const float*)d_in[18];
    const float* b_pl1 = (const float*)d_in[19];
    const float* w_pl2 = (const float*)d_in[20];
    const float* b_pl2 = (const float*)d_in[21];
    const float* w_pl3 = (const float*)d_in[22];
    const float* b_pl3 = (const float*)d_in[23];
    const float* w_pl4 = (const float*)d_in[24];
    const float* b_pl4 = (const float*)d_in[25];
    float* out = (float*)d_out;

    prep_wA_kernel<<<(3 * 36 * 2048 + 255) / 256, 256>>>(w_s1, w_s2, w_s3);
    init_out_kernel<<<(64 * 224 + 255) / 256, 256>>>(b_pl1, b_pl2, b_pl3, out);

    uint4* wAd;
    cudaGetSymbolAddress((void**)&wAd, g_wA);

    // dynamic smem: 1024 + 2 * NP*80 bytes
    const int sm1 = 1024 + 2 * (2 + 2) * 130 * 80;  // 84224
    const int sm2 = 1024 + 2 * (4 + 2) * 66 * 80;   // 64384
    const int sm3 = 1024 + 2 * (8 + 2) * 34 * 80;   // 55424
    cudaFuncSetAttribute(conv_mma_kernel<64, 128, 7, 2, 0>,
                         cudaFuncAttributeMaxDynamicSharedMemorySize, sm1);
    cudaFuncSetAttribute(conv_mma_kernel<32, 64, 6, 4, 128>,
                         cudaFuncAttributeMaxDynamicSharedMemorySize, sm2);
    cudaFuncSetAttribute(conv_mma_kernel<16, 32, 5, 8, 192>,
                         cudaFuncAttributeMaxDynamicSharedMemorySize, sm3);

    conv_mma_kernel<64, 128, 7, 2, 0><<<64 * 32, 256, sm1>>>(
        p2, wAd + 0 * 36 * 512, b_s1, w_t1, b_t1, w_pl1, out);
    conv_mma_kernel<32, 64, 6, 4, 128><<<64 * 8, 256, sm2>>>(
        p3, wAd + 1 * 36 * 512, b_s2, w_t2, b_t2, w_pl2, out);
    conv_mma_kernel<16, 32, 5, 8, 192><<<64 * 2, 256, sm3>>>(
        p4, wAd + 2 * 36 * 512, b_s3, w_t3, b_t3, w_pl3, out);
    p5_kernel<<<64, 256>>>(p5, w_t4, b_t4, w_pl4, b_pl4, out);
}

// round 10
// speedup vs baseline: 1.1641x; 1.1160x over previous
#include <cuda_runtime.h>
#include <cuda_fp16.h>
#include <cstdint>

// ---------------------------------------------------------------------------
// FPN head via legacy tensor cores (mma.sync m16n8k16 f16, fp32 accum).
// R10: 2 blocks/SM (128o x 128n tile, 64 accs, <=128 regs) + ALL levels and
// the p5 path fused into ONE kernel launch (branch on blockIdx) -> cross-
// block latency hiding replaces double buffering; no sequential launch tails.
// Output: [64, 240] fp32  (c1:128 | c2:64 | c3:32 | c4:16)
// ---------------------------------------------------------------------------

typedef unsigned int u32;

// A fragment image: [l][gi(36)][rg(8)][ks(2)][lane(32)] x uint4
__device__ uint4 g_wA[3 * 36 * 8 * 2 * 32];

#define SMEM_BYTES 22272

// ---- PTX helpers ----------------------------------------------------------
__device__ __forceinline__ u32 smem_u32(const void* p) {
    u32 a;
    asm("{ .reg .u64 t; cvta.to.shared.u64 t, %1; cvt.u32.u64 %0, t; }"
        : "=r"(a) : "l"(p));
    return a;
}
__device__ __forceinline__ void ldm_x4(u32* r, u32 addr) {
    asm volatile("ldmatrix.sync.aligned.m8n8.x4.shared.b16 {%0,%1,%2,%3}, [%4];"
                 : "=r"(r[0]), "=r"(r[1]), "=r"(r[2]), "=r"(r[3]) : "r"(addr));
}
__device__ __forceinline__ void mma16816(float* d, const uint4 a, u32 b0, u32 b1) {
    asm volatile(
        "mma.sync.aligned.m16n8k16.row.col.f32.f16.f16.f32 "
        "{%0,%1,%2,%3}, {%4,%5,%6,%7}, {%8,%9}, {%0,%1,%2,%3};"
        : "+f"(d[0]), "+f"(d[1]), "+f"(d[2]), "+f"(d[3])
        : "r"(a.x), "r"(a.y), "r"(a.z), "r"(a.w), "r"(b0), "r"(b1));
}

// ---- weight prep: w[o][c][tap] fp32 -> A fragment image -------------------
__global__ void prep_wA_kernel(const float* __restrict__ w1,
                               const float* __restrict__ w2,
                               const float* __restrict__ w3) {
    int i = blockIdx.x * 256 + threadIdx.x;          // one u32 each
    if (i >= 3 * 36 * 2048) return;
    int q    = i & 3;
    int lane = (i >> 2) & 31;
    int ks   = (i >> 7) & 1;
    int rg   = (i >> 8) & 7;
    int gi   = (i >> 11) % 36;
    int l    = i / (36 << 11);
    const float* src = (l == 0) ? w1 : (l == 1) ? w2 : w3;
    int o = rg * 16 + (lane >> 2) + (q & 1) * 8;
    int k = ks * 16 + (lane & 3) * 2 + (q >> 1) * 8;
    int c = (gi / 9) * 32 + k;
    int tap = gi % 9;
    __half2 hv = __floats2half2_rn(src[o * 1152 + c * 9 + tap],
                                   src[o * 1152 + (c + 1) * 9 + tap]);
    ((u32*)g_wA)[i] = *(u32*)&hv;
}

// ---- out init: bpl bias for c1..c3 regions --------------------------------
__global__ void init_out_kernel(const float* __restrict__ bpl1,
                                const float* __restrict__ bpl2,
                                const float* __restrict__ bpl3,
                                float* __restrict__ out) {
    int i = blockIdx.x * blockDim.x + threadIdx.x;
    if (i >= 64 * 224) return;
    int j = i % 224;
    out[(i / 224) * 240 + j] = (j < 128) ? bpl1[0] : (j < 192) ? bpl2[0] : bpl3[0];
}

// ---- conv tile worker ------------------------------------------------------
// 256 threads = 8 warps as 2(m) x 4(n). Warp tile 64o x 32n.
// Block tile: 128 o x 128 n = R rows x TW cols (TW-wide stripe of image).
// SMEM: sCol(128f)@0, B @1024: [(R+2)*(TW+2) pos][40 f16], XOR swizzle.
template <int H, int W, int TW, int LTW, int R, int BASE>
__device__ void conv_tile_impl(
    int tbid, const float* __restrict__ x, const uint4* __restrict__ wA,
    const float* __restrict__ bs, const float* __restrict__ wt,
    const float* __restrict__ bt, const float* __restrict__ wpl,
    float* __restrict__ out, char* smem) {
    constexpr int NW = TW + 2;
    constexpr int NP = (R + 2) * NW;
    constexpr int B_OFF = 1024;
    constexpr int CT = W / TW;

    float* sCol = (float*)smem;
    const u32 smu = smem_u32(smem);
    const u32 bbase = smu + B_OFF;

    const int tid = threadIdx.x;
    const int warp = tid >> 5;
    const int lane = tid & 31;
    const int warpm = warp & 1;
    const int warpn = warp >> 1;   // 0..3, each 32 n

    const int TPB = (H / R) * CT;
    const int b = tbid / TPB;
    const int rem = tbid - b * TPB;
    const int h0 = (rem / CT) * R;
    const int w0 = (rem - (rem / CT) * CT) * TW;
    const float* xb = x + (size_t)b * 128 * H * W;

    if (tid < R * TW) sCol[tid] = 0.f;

    // hoisted B-tile geometry (2 ldmatrix groups, each 16 n)
    int p0[2];
#pragma unroll
    for (int j = 0; j < 2; j++) {
        int ng = warpn * 32 + j * 16 + (lane >> 4) * 8;
        int trow = ng >> LTW;
        int tcol = ng & (TW - 1);
        p0[j] = trow * NW + tcol + (lane & 7);
    }
    const int kbh = (lane >> 3) & 1;

    float d[4][4][4];
#pragma unroll
    for (int mi = 0; mi < 4; mi++)
#pragma unroll
        for (int nj = 0; nj < 4; nj++)
#pragma unroll
            for (int q = 0; q < 4; q++) d[mi][nj][q] = 0.f;

    for (int cc = 0; cc < 4; cc++) {
        __syncthreads();  // protect prior chunk's readers
        // stage B: 32 channels x NP halo positions (halo cols load real data
        // when the stripe is interior; OOB -> zero)
        {
            const int c0ch = cc * 32;
            const int cp = tid >> 4;
            for (int p = tid & 15; p < NP; p += 16) {
                int r = p / NW;
                int w = p - r * NW;
                int gh = h0 + r - 1;
                int gw = w0 + w - 1;
                float v0 = 0.f, v1 = 0.f;
                if (gh >= 0 && gh < H && (unsigned)gw < (unsigned)W) {
                    const float* bp =
                        xb + ((size_t)(c0ch + 2 * cp) * H + gh) * W + gw;
                    v0 = bp[0];
                    v1 = bp[H * W];
                }
                __half2 hv = __floats2half2_rn(v0, v1);
                int word = p * 20 + ((((cp >> 2) ^ (p & 3)) << 2)) + (cp & 3);
                *(__half2*)(smem + B_OFF + word * 4) = hv;
            }
        }
        __syncthreads();

        // 9 taps straight-line: A via LDG.128 (L1-cached), B via ldmatrix
#pragma unroll
        for (int tap = 0; tap < 9; tap++) {
            const int gi = cc * 9 + tap;
            const int dy = tap / 3;
            const int dx = tap - dy * 3;
            const int pofs = dy * NW + dx;
#pragma unroll
            for (int ks = 0; ks < 2; ks++) {
                uint4 a[4];
#pragma unroll
                for (int mi = 0; mi < 4; mi++) {
                    int rg = warpm * 4 + mi;
                    a[mi] = wA[((gi * 8 + rg) * 2 + ks) * 32 + lane];
                }
                const int kb = ks * 2 + kbh;
#pragma unroll
                for (int j = 0; j < 2; j++) {
                    int p = p0[j] + pofs;
                    u32 bf[4];
                    ldm_x4(bf, bbase + p * 80 + ((kb ^ (p & 3)) << 4));
#pragma unroll
                    for (int mi = 0; mi < 4; mi++) {
                        mma16816(d[mi][2 * j], a[mi], bf[0], bf[1]);
                        mma16816(d[mi][2 * j + 1], a[mi], bf[2], bf[3]);
                    }
                }
            }
        }
    }

    // ---- epilogue: bias + ReLU + dot(w_t), reduce, pool -------------------
    const int g = lane >> 2;
    const int tid4 = lane & 3;
    float bsv[4][2], wtv[4][2];
#pragma unroll
    for (int mi = 0; mi < 4; mi++)
#pragma unroll
        for (int hh = 0; hh < 2; hh++) {
            int o = warpm * 64 + mi * 16 + hh * 8 + g;
            bsv[mi][hh] = bs[o];
            wtv[mi][hh] = wt[o];
        }
    __syncthreads();
#pragma unroll
    for (int nj = 0; nj < 4; nj++) {
        float v0 = 0.f, v1 = 0.f;
#pragma unroll
        for (int mi = 0; mi < 4; mi++) {
            v0 += fmaxf(d[mi][nj][0] + bsv[mi][0], 0.f) * wtv[mi][0]
                + fmaxf(d[mi][nj][2] + bsv[mi][1], 0.f) * wtv[mi][1];
            v1 += fmaxf(d[mi][nj][1] + bsv[mi][0], 0.f) * wtv[mi][0]
                + fmaxf(d[mi][nj][3] + bsv[mi][1], 0.f) * wtv[mi][1];
        }
        v0 += __shfl_xor_sync(0xffffffffu, v0, 4);
        v0 += __shfl_xor_sync(0xffffffffu, v0, 8);
        v0 += __shfl_xor_sync(0xffffffffu, v0, 16);
        v1 += __shfl_xor_sync(0xffffffffu, v1, 4);
        v1 += __shfl_xor_sync(0xffffffffu, v1, 8);
        v1 += __shfl_xor_sync(0xffffffffu, v1, 16);
        if (lane < 4) {
            int n = warpn * 32 + nj * 8 + tid4 * 2;
            atomicAdd(&sCol[n], v0);
            atomicAdd(&sCol[n + 1], v1);
        }
    }
    __syncthreads();

    if (tid < TW) {
        const float btv = bt[0];
        float s = 0.f;
#pragma unroll
        for (int r = 0; r < R; r++)
            s += wpl[h0 + r] * (sCol[r * TW + tid] + btv);
        atomicAdd(&out[b * 240 + BASE + w0 + tid], s);
    }
}

// ---- p5 tile: tidy 1x1 (512->1) + pool over h=8, memory bound -------------
__device__ void p5_tile(int b, const float* __restrict__ p5,
                        const float* __restrict__ wt,
                        const float* __restrict__ bt,
                        const float* __restrict__ wpl,
                        const float* __restrict__ bpl,
                        float* __restrict__ out, char* smem) {
    float* red = (float*)smem;          // 256 floats
    float* spl = (float*)smem + 256;    // 8 floats
    const int tid = threadIdx.x;
    const int w = tid & 15;
    const int g = tid >> 4;
    if (tid < 8) spl[tid] = wpl[tid];
    __syncthreads();

    const float* pb = p5 + (size_t)b * 512 * 8 * 16;
    float accv = 0.f;
    for (int c = g; c < 512; c += 16) {
        float wc = wt[c];
        const float* row = pb + (size_t)c * 8 * 16 + w;
#pragma unroll
        for (int h = 0; h < 8; h++)
            accv = fmaf(wc * spl[h], row[h * 16], accv);
    }
    red[tid] = accv;
    __syncthreads();
    if (tid < 16) {
        float s = 0.f;
#pragma unroll
        for (int gg = 0; gg < 16; gg++) s += red[gg * 16 + tid];
        float sumpl = 0.f;
#pragma unroll
        for (int h = 0; h < 8; h++) sumpl += spl[h];
        out[b * 240 + 224 + tid] = s + bt[0] * sumpl + bpl[0];
    }
}

// ---- fused kernel: all conv levels + p5 in one grid ------------------------
// blocks: [0,4096) L1 | [4096,5120) L2 | [5120,5376) L3 | [5376,5440) p5
__global__ void __launch_bounds__(256, 2)
fused_kernel(const float* __restrict__ p2, const float* __restrict__ p3,
             const float* __restrict__ p4, const float* __restrict__ p5,
             const uint4* __restrict__ wA,
             const float* __restrict__ bs1, const float* __restrict__ bs2,
             const float* __restrict__ bs3,
             const float* __restrict__ wt1, const float* __restrict__ bt1,
             const float* __restrict__ wt2, const float* __restrict__ bt2,
             const float* __restrict__ wt3, const float* __restrict__ bt3,
             const float* __restrict__ wt4, const float* __restrict__ bt4,
             const float* __restrict__ wpl1, const float* __restrict__ wpl2,
             const float* __restrict__ wpl3, const float* __restrict__ wpl4,
             const float* __restrict__ bpl4,
             float* __restrict__ out) {
    extern __shared__ char smem[];
    const int bid = blockIdx.x;
    if (bid < 4096) {
        conv_tile_impl<64, 128, 64, 6, 2, 0>(bid, p2, wA, bs1, wt1, bt1,
                                             wpl1, out, smem);
    } else if (bid < 5120) {
        conv_tile_impl<32, 64, 64, 6, 2, 128>(bid - 4096, p3, wA + 36 * 512,
                                              bs2, wt2, bt2, wpl2, out, smem);
    } else if (bid < 5376) {
        conv_tile_impl<16, 32, 32, 5, 4, 192>(bid - 5120, p4, wA + 72 * 512,
                                              bs3, wt3, bt3, wpl3, out, smem);
    } else {
        p5_tile(bid - 5376, p5, wt4, bt4, wpl4, bpl4, out, smem);
    }
}

// ---------------------------------------------------------------------------
extern "C" void kernel_launch(void* const* d_in, const int* in_sizes, int n_in,
                              void* d_out, int out_size) {
    const float* p2 = (const float*)d_in[0];
    const float* p3 = (const float*)d_in[1];
    const float* p4 = (const float*)d_in[2];
    const float* p5 = (const float*)d_in[3];
    const float* w_s1 = (const float*)d_in[4];
    const float* b_s1 = (const float*)d_in[5];
    const float* w_s2 = (const float*)d_in[6];
    const float* b_s2 = (const float*)d_in[7];
    const float* w_s3 = (const float*)d_in[8];
    const float* b_s3 = (const float*)d_in[9];
    const float* w_t1 = (const float*)d_in[10];
    const float* b_t1 = (const float*)d_in[11];
    const float* w_t2 = (const float*)d_in[12];
    const float* b_t2 = (const float*)d_in[13];
    const float* w_t3 = (const float*)d_in[14];
    const float* b_t3 = (const float*)d_in[15];
    const float* w_t4 = (const float*)d_in[16];
    const float* b_t4 = (const float*)d_in[17];
    const float* w_pl1 = (const float*)d_in[18];
    const float* b_pl1 = (const float*)d_in[19];
    const float* w_pl2 = (const float*)d_in[20];
    const float* b_pl2 = (const float*)d_in[21];
    const float* w_pl3 = (const float*)d_in[22];
    const float* b_pl3 = (const float*)d_in[23];
    const float* w_pl4 = (const float*)d_in[24];
    const float* b_pl4 = (const float*)d_in[25];
    float* out = (float*)d_out;

    prep_wA_kernel<<<(3 * 36 * 2048 + 255) / 256, 256>>>(w_s1, w_s2, w_s3);
    init_out_kernel<<<(64 * 224 + 255) / 256, 256>>>(b_pl1, b_pl2, b_pl3, out);

    uint4* wAd;
    cudaGetSymbolAddress((void**)&wAd, g_wA);

    fused_kernel<<<5440, 256, SMEM_BYTES>>>(
        p2, p3, p4, p5, wAd,
        b_s1, b_s2, b_s3,
        w_t1, b_t1, w_t2, b_t2, w_t3, b_t3, w_t4, b_t4,
        w_pl1, w_pl2, w_pl3, w_pl4, b_pl4, out);
}

// round 11
// speedup vs baseline: 1.1706x; 1.0056x over previous
#include <cuda_runtime.h>
#include <cuda_fp16.h>
#include <cstdint>

// ---------------------------------------------------------------------------
// FPN head via legacy tensor cores (mma.sync m16n8k16 f16, fp32 accum).
// R11: R10 (2 blocks/SM, fused single launch) + double-buffered stage-ahead
// B staging + float4-vectorized interior staging (halo cols scalar).
// Output: [64, 240] fp32  (c1:128 | c2:64 | c3:32 | c4:16)
// ---------------------------------------------------------------------------

typedef unsigned int u32;

// A fragment image: [l][gi(36)][rg(8)][ks(2)][lane(32)] x uint4
__device__ uint4 g_wA[3 * 36 * 8 * 2 * 32];

#define SMEM_BYTES 43264   // 1024 + 2 * 21120 (largest level)

// ---- PTX helpers ----------------------------------------------------------
__device__ __forceinline__ u32 smem_u32(const void* p) {
    u32 a;
    asm("{ .reg .u64 t; cvta.to.shared.u64 t, %1; cvt.u32.u64 %0, t; }"
        : "=r"(a) : "l"(p));
    return a;
}
__device__ __forceinline__ void ldm_x4(u32* r, u32 addr) {
    asm volatile("ldmatrix.sync.aligned.m8n8.x4.shared.b16 {%0,%1,%2,%3}, [%4];"
                 : "=r"(r[0]), "=r"(r[1]), "=r"(r[2]), "=r"(r[3]) : "r"(addr));
}
__device__ __forceinline__ void mma16816(float* d, const uint4 a, u32 b0, u32 b1) {
    asm volatile(
        "mma.sync.aligned.m16n8k16.row.col.f32.f16.f16.f32 "
        "{%0,%1,%2,%3}, {%4,%5,%6,%7}, {%8,%9}, {%0,%1,%2,%3};"
        : "+f"(d[0]), "+f"(d[1]), "+f"(d[2]), "+f"(d[3])
        : "r"(a.x), "r"(a.y), "r"(a.z), "r"(a.w), "r"(b0), "r"(b1));
}

// ---- weight prep: w[o][c][tap] fp32 -> A fragment image -------------------
__global__ void prep_wA_kernel(const float* __restrict__ w1,
                               const float* __restrict__ w2,
                               const float* __restrict__ w3) {
    int i = blockIdx.x * 256 + threadIdx.x;          // one u32 each
    if (i >= 3 * 36 * 2048) return;
    int q    = i & 3;
    int lane = (i >> 2) & 31;
    int ks   = (i >> 7) & 1;
    int rg   = (i >> 8) & 7;
    int gi   = (i >> 11) % 36;
    int l    = i / (36 << 11);
    const float* src = (l == 0) ? w1 : (l == 1) ? w2 : w3;
    int o = rg * 16 + (lane >> 2) + (q & 1) * 8;
    int k = ks * 16 + (lane & 3) * 2 + (q >> 1) * 8;
    int c = (gi / 9) * 32 + k;
    int tap = gi % 9;
    __half2 hv = __floats2half2_rn(src[o * 1152 + c * 9 + tap],
                                   src[o * 1152 + (c + 1) * 9 + tap]);
    ((u32*)g_wA)[i] = *(u32*)&hv;
}

// ---- out init: bpl bias for c1..c3 regions --------------------------------
__global__ void init_out_kernel(const float* __restrict__ bpl1,
                                const float* __restrict__ bpl2,
                                const float* __restrict__ bpl3,
                                float* __restrict__ out) {
    int i = blockIdx.x * blockDim.x + threadIdx.x;
    if (i >= 64 * 224) return;
    int j = i % 224;
    out[(i / 224) * 240 + j] = (j < 128) ? bpl1[0] : (j < 192) ? bpl2[0] : bpl3[0];
}

// ---- conv tile worker ------------------------------------------------------
// 256 threads = 8 warps as 2(m) x 4(n). Warp tile 64o x 32n.
// Block tile: 128 o x 128 n = R rows x TW cols (TW-wide stripe of image).
// SMEM: sCol(128f)@0, B double buffer @1024:
//   [(R+2)*(TW+2) pos][40 f16], 16B-block XOR swizzle.
template <int H, int W, int TW, int LTW, int R, int BASE>
__device__ void conv_tile_impl(
    int tbid, const float* __restrict__ x, const uint4* __restrict__ wA,
    const float* __restrict__ bs, const float* __restrict__ wt,
    const float* __restrict__ bt, const float* __restrict__ wpl,
    float* __restrict__ out, char* smem) {
    constexpr int NW = TW + 2;
    constexpr int NP = (R + 2) * NW;
    constexpr int B_OFF = 1024;
    constexpr int BBYTES = NP * 80;
    constexpr int CT = W / TW;
    constexpr int TW4 = TW / 4;

    float* sCol = (float*)smem;
    const u32 smu = smem_u32(smem);

    const int tid = threadIdx.x;
    const int warp = tid >> 5;
    const int lane = tid & 31;
    const int warpm = warp & 1;
    const int warpn = warp >> 1;   // 0..3, each 32 n

    const int TPB = (H / R) * CT;
    const int b = tbid / TPB;
    const int rem = tbid - b * TPB;
    const int h0 = (rem / CT) * R;
    const int w0 = (rem - (rem / CT) * CT) * TW;
    const float* xb = x + (size_t)b * 128 * H * W;

    if (tid < R * TW) sCol[tid] = 0.f;

    // hoisted B-tile geometry (2 ldmatrix groups, each 16 n)
    int p0[2];
#pragma unroll
    for (int j = 0; j < 2; j++) {
        int ng = warpn * 32 + j * 16 + (lane >> 4) * 8;
        int trow = ng >> LTW;
        int tcol = ng & (TW - 1);
        p0[j] = trow * NW + tcol + (lane & 7);
    }
    const int kbh = (lane >> 3) & 1;

    float d[4][4][4];
#pragma unroll
    for (int mi = 0; mi < 4; mi++)
#pragma unroll
        for (int nj = 0; nj < 4; nj++)
#pragma unroll
            for (int q = 0; q < 4; q++) d[mi][nj][q] = 0.f;

    // ---- staging: float4 interior + scalar halo columns -------------------
#define STAGE_B(ccv, bufv)                                                   \
    do {                                                                     \
        char* dstc = smem + B_OFF + (bufv) * BBYTES;                         \
        const int cp = tid >> 4;                                             \
        const float* xc0 = xb + (size_t)((ccv) * 32 + 2 * cp) * H * W;       \
        _Pragma("unroll 1")                                                  \
        for (int it = tid & 15; it < (R + 2) * 2; it += 16) {                \
            int r = it >> 1;                                                 \
            int w = (it & 1) * (NW - 1);                                     \
            int gh = h0 + r - 1;                                             \
            int gw = w0 + w - 1;                                             \
            float v0 = 0.f, v1 = 0.f;                                        \
            if (gh >= 0 && gh < H && (unsigned)gw < (unsigned)W) {           \
                const float* bp = xc0 + gh * W + gw;                         \
                v0 = bp[0];                                                  \
                v1 = bp[H * W];                                              \
            }                                                                \
            int p = r * NW + w;                                              \
            __half2 hv = __floats2half2_rn(v0, v1);                         \
            int word = p * 20 + ((((cp >> 2) ^ (p & 3)) << 2)) + (cp & 3);   \
            *(__half2*)(dstc + word * 4) = hv;                               \
        }                                                                    \
        _Pragma("unroll 1")                                                  \
        for (int it = tid & 15; it < (R + 2) * TW4; it += 16) {              \
            int r = it / TW4;                                                \
            int w4 = (it - r * TW4) * 4;                                     \
            int gh = h0 + r - 1;                                             \
            float4 v0 = {0.f, 0.f, 0.f, 0.f}, v1 = v0;                       \
            if (gh >= 0 && gh < H) {                                         \
                const float* bp = xc0 + gh * W + (w0 + w4);                  \
                v0 = *(const float4*)bp;                                     \
                v1 = *(const float4*)(bp + H * W);                           \
            }                                                                \
            const float* f0 = (const float*)&v0;                            \
            const float* f1 = (const float*)&v1;                            \
            _Pragma("unroll")                                                \
            for (int dw = 0; dw < 4; dw++) {                                 \
                int p = r * NW + w4 + dw + 1;                                \
                __half2 hv = __floats2half2_rn(f0[dw], f1[dw]);              \
                int word = p * 20 + ((((cp >> 2) ^ (p & 3)) << 2)) + (cp & 3);\
                *(__half2*)(dstc + word * 4) = hv;                           \
            }                                                                \
        }                                                                    \
    } while (0)

    STAGE_B(0, 0);
    __syncthreads();

    for (int cc = 0; cc < 4; cc++) {
        // stage-ahead into the other buffer while this chunk's MMAs run
        if (cc < 3) STAGE_B(cc + 1, (cc + 1) & 1);

        const u32 bbase = smu + B_OFF + (cc & 1) * BBYTES;
#pragma unroll
        for (int tap = 0; tap < 9; tap++) {
            const int gi = cc * 9 + tap;
            const int dy = tap / 3;
            const int dx = tap - dy * 3;
            const int pofs = dy * NW + dx;
#pragma unroll
            for (int ks = 0; ks < 2; ks++) {
                uint4 a[4];
#pragma unroll
                for (int mi = 0; mi < 4; mi++) {
                    int rg = warpm * 4 + mi;
                    a[mi] = wA[((gi * 8 + rg) * 2 + ks) * 32 + lane];
                }
                const int kb = ks * 2 + kbh;
#pragma unroll
                for (int j = 0; j < 2; j++) {
                    int p = p0[j] + pofs;
                    u32 bf[4];
                    ldm_x4(bf, bbase + p * 80 + ((kb ^ (p & 3)) << 4));
#pragma unroll
                    for (int mi = 0; mi < 4; mi++) {
                        mma16816(d[mi][2 * j], a[mi], bf[0], bf[1]);
                        mma16816(d[mi][2 * j + 1], a[mi], bf[2], bf[3]);
                    }
                }
            }
        }
        __syncthreads();
    }

    // ---- epilogue: bias + ReLU + dot(w_t), reduce, pool -------------------
    const int g = lane >> 2;
    const int tid4 = lane & 3;
    float bsv[4][2], wtv[4][2];
#pragma unroll
    for (int mi = 0; mi < 4; mi++)
#pragma unroll
        for (int hh = 0; hh < 2; hh++) {
            int o = warpm * 64 + mi * 16 + hh * 8 + g;
            bsv[mi][hh] = bs[o];
            wtv[mi][hh] = wt[o];
        }
#pragma unroll
    for (int nj = 0; nj < 4; nj++) {
        float v0 = 0.f, v1 = 0.f;
#pragma unroll
        for (int mi = 0; mi < 4; mi++) {
            v0 += fmaxf(d[mi][nj][0] + bsv[mi][0], 0.f) * wtv[mi][0]
                + fmaxf(d[mi][nj][2] + bsv[mi][1], 0.f) * wtv[mi][1];
            v1 += fmaxf(d[mi][nj][1] + bsv[mi][0], 0.f) * wtv[mi][0]
                + fmaxf(d[mi][nj][3] + bsv[mi][1], 0.f) * wtv[mi][1];
        }
        v0 += __shfl_xor_sync(0xffffffffu, v0, 4);
        v0 += __shfl_xor_sync(0xffffffffu, v0, 8);
        v0 += __shfl_xor_sync(0xffffffffu, v0, 16);
        v1 += __shfl_xor_sync(0xffffffffu, v1, 4);
        v1 += __shfl_xor_sync(0xffffffffu, v1, 8);
        v1 += __shfl_xor_sync(0xffffffffu, v1, 16);
        if (lane < 4) {
            int n = warpn * 32 + nj * 8 + tid4 * 2;
            atomicAdd(&sCol[n], v0);
            atomicAdd(&sCol[n + 1], v1);
        }
    }
    __syncthreads();

    if (tid < TW) {
        const float btv = bt[0];
        float s = 0.f;
#pragma unroll
        for (int r = 0; r < R; r++)
            s += wpl[h0 + r] * (sCol[r * TW + tid] + btv);
        atomicAdd(&out[b * 240 + BASE + w0 + tid], s);
    }
}

// ---- p5 tile: tidy 1x1 (512->1) + pool over h=8, memory bound -------------
__device__ void p5_tile(int b, const float* __restrict__ p5,
                        const float* __restrict__ wt,
                        const float* __restrict__ bt,
                        const float* __restrict__ wpl,
                        const float* __restrict__ bpl,
                        float* __restrict__ out, char* smem) {
    float* red = (float*)smem;          // 256 floats
    float* spl = (float*)smem + 256;    // 8 floats
    const int tid = threadIdx.x;
    const int w = tid & 15;
    const int g = tid >> 4;
    if (tid < 8) spl[tid] = wpl[tid];
    __syncthreads();

    const float* pb = p5 + (size_t)b * 512 * 8 * 16;
    float accv = 0.f;
    for (int c = g; c < 512; c += 16) {
        float wc = wt[c];
        const float* row = pb + (size_t)c * 8 * 16 + w;
#pragma unroll
        for (int h = 0; h < 8; h++)
            accv = fmaf(wc * spl[h], row[h * 16], accv);
    }
    red[tid] = accv;
    __syncthreads();
    if (tid < 16) {
        float s = 0.f;
#pragma unroll
        for (int gg = 0; gg < 16; gg++) s += red[gg * 16 + tid];
        float sumpl = 0.f;
#pragma unroll
        for (int h = 0; h < 8; h++) sumpl += spl[h];
        out[b * 240 + 224 + tid] = s + bt[0] * sumpl + bpl[0];
    }
}

// ---- fused kernel: all conv levels + p5 in one grid ------------------------
// blocks: [0,4096) L1 | [4096,5120) L2 | [5120,5376) L3 | [5376,5440) p5
__global__ void __launch_bounds__(256, 2)
fused_kernel(const float* __restrict__ p2, const float* __restrict__ p3,
             const float* __restrict__ p4, const float* __restrict__ p5,
             const uint4* __restrict__ wA,
             const float* __restrict__ bs1, const float* __restrict__ bs2,
             const float* __restrict__ bs3,
             const float* __restrict__ wt1, const float* __restrict__ bt1,
             const float* __restrict__ wt2, const float* __restrict__ bt2,
             const float* __restrict__ wt3, const float* __restrict__ bt3,
             const float* __restrict__ wt4, const float* __restrict__ bt4,
             const float* __restrict__ wpl1, const float* __restrict__ wpl2,
             const float* __restrict__ wpl3, const float* __restrict__ wpl4,
             const float* __restrict__ bpl4,
             float* __restrict__ out) {
    extern __shared__ char smem[];
    const int bid = blockIdx.x;
    if (bid < 4096) {
        conv_tile_impl<64, 128, 64, 6, 2, 0>(bid, p2, wA, bs1, wt1, bt1,
                                             wpl1, out, smem);
    } else if (bid < 5120) {
        conv_tile_impl<32, 64, 64, 6, 2, 128>(bid - 4096, p3, wA + 36 * 512,
                                              bs2, wt2, bt2, wpl2, out, smem);
    } else if (bid < 5376) {
        conv_tile_impl<16, 32, 32, 5, 4, 192>(bid - 5120, p4, wA + 72 * 512,
                                              bs3, wt3, bt3, wpl3, out, smem);
    } else {
        p5_tile(bid - 5376, p5, wt4, bt4, wpl4, bpl4, out, smem);
    }
}

// ---------------------------------------------------------------------------
extern "C" void kernel_launch(void* const* d_in, const int* in_sizes, int n_in,
                              void* d_out, int out_size) {
    const float* p2 = (const float*)d_in[0];
    const float* p3 = (const float*)d_in[1];
    const float* p4 = (const float*)d_in[2];
    const float* p5 = (const float*)d_in[3];
    const float* w_s1 = (const float*)d_in[4];
    const float* b_s1 = (const float*)d_in[5];
    const float* w_s2 = (const float*)d_in[6];
    const float* b_s2 = (const float*)d_in[7];
    const float* w_s3 = (const float*)d_in[8];
    const float* b_s3 = (const float*)d_in[9];
    const float* w_t1 = (const float*)d_in[10];
    const float* b_t1 = (const float*)d_in[11];
    const float* w_t2 = (const float*)d_in[12];
    const float* b_t2 = (const float*)d_in[13];
    const float* w_t3 = (const float*)d_in[14];
    const float* b_t3 = (const float*)d_in[15];
    const float* w_t4 = (const float*)d_in[16];
    const float* b_t4 = (const float*)d_in[17];
    const float* w_pl1 = (const float*)d_in[18];
    const float* b_pl1 = (const float*)d_in[19];
    const float* w_pl2 = (const float*)d_in[20];
    const float* b_pl2 = (const float*)d_in[21];
    const float* w_pl3 = (const float*)d_in[22];
    const float* b_pl3 = (const float*)d_in[23];
    const float* w_pl4 = (const float*)d_in[24];
    const float* b_pl4 = (const float*)d_in[25];
    float* out = (float*)d_out;

    prep_wA_kernel<<<(3 * 36 * 2048 + 255) / 256, 256>>>(w_s1, w_s2, w_s3);
    init_out_kernel<<<(64 * 224 + 255) / 256, 256>>>(b_pl1, b_pl2, b_pl3, out);

    uint4* wAd;
    cudaGetSymbolAddress((void**)&wAd, g_wA);

    cudaFuncSetAttribute(fused_kernel,
                         cudaFuncAttributeMaxDynamicSharedMemorySize,
                         SMEM_BYTES);
    fused_kernel<<<5440, 256, SMEM_BYTES>>>(
        p2, p3, p4, p5, wAd,
        b_s1, b_s2, b_s3,
        w_t1, b_t1, w_t2, b_t2, w_t3, b_t3, w_t4, b_t4,
        w_pl1, w_pl2, w_pl3, w_pl4, b_pl4, out);
}

// round 12
// speedup vs baseline: 1.3238x; 1.1309x over previous
#include <cuda_runtime.h>
#include <cuda_fp16.h>
#include <cstdint>

// ---------------------------------------------------------------------------
// FPN head via legacy tensor cores (mma.sync m16n8k16 f16, fp32 accum).
// R12: 4 blocks/SM (128 threads, 4 warps 2m x 2n, block tile 128o x 64n,
// ~115 regs, 11.9KB smem) -> 4 independent barrier domains per SM; staging /
// barrier bubbles of one block are covered by the other three.
// Fused single launch for all levels + p5. A fragment-direct via LDG.128.
// Output: [64, 240] fp32  (c1:128 | c2:64 | c3:32 | c4:16)
// ---------------------------------------------------------------------------

typedef unsigned int u32;

// A fragment image: [l][gi(36)][rg(8)][ks(2)][lane(32)] x uint4
__device__ uint4 g_wA[3 * 36 * 8 * 2 * 32];

// per-block smem: sCol(64f)/p5 scratch @0, B @1024: (R+2)*(TW+2)*80 bytes
#define SMEM_BYTES 11904   // 1024 + 4*34*80

// ---- PTX helpers ----------------------------------------------------------
__device__ __forceinline__ u32 smem_u32(const void* p) {
    u32 a;
    asm("{ .reg .u64 t; cvta.to.shared.u64 t, %1; cvt.u32.u64 %0, t; }"
        : "=r"(a) : "l"(p));
    return a;
}
__device__ __forceinline__ void ldm_x4(u32* r, u32 addr) {
    asm volatile("ldmatrix.sync.aligned.m8n8.x4.shared.b16 {%0,%1,%2,%3}, [%4];"
                 : "=r"(r[0]), "=r"(r[1]), "=r"(r[2]), "=r"(r[3]) : "r"(addr));
}
__device__ __forceinline__ void mma16816(float* d, const uint4 a, u32 b0, u32 b1) {
    asm volatile(
        "mma.sync.aligned.m16n8k16.row.col.f32.f16.f16.f32 "
        "{%0,%1,%2,%3}, {%4,%5,%6,%7}, {%8,%9}, {%0,%1,%2,%3};"
        : "+f"(d[0]), "+f"(d[1]), "+f"(d[2]), "+f"(d[3])
        : "r"(a.x), "r"(a.y), "r"(a.z), "r"(a.w), "r"(b0), "r"(b1));
}

// ---- weight prep: w[o][c][tap] fp32 -> A fragment image -------------------
__global__ void prep_wA_kernel(const float* __restrict__ w1,
                               const float* __restrict__ w2,
                               const float* __restrict__ w3) {
    int i = blockIdx.x * 256 + threadIdx.x;          // one u32 each
    if (i >= 3 * 36 * 2048) return;
    int q    = i & 3;
    int lane = (i >> 2) & 31;
    int ks   = (i >> 7) & 1;
    int rg   = (i >> 8) & 7;
    int gi   = (i >> 11) % 36;
    int l    = i / (36 << 11);
    const float* src = (l == 0) ? w1 : (l == 1) ? w2 : w3;
    int o = rg * 16 + (lane >> 2) + (q & 1) * 8;
    int k = ks * 16 + (lane & 3) * 2 + (q >> 1) * 8;
    int c = (gi / 9) * 32 + k;
    int tap = gi % 9;
    __half2 hv = __floats2half2_rn(src[o * 1152 + c * 9 + tap],
                                   src[o * 1152 + (c + 1) * 9 + tap]);
    ((u32*)g_wA)[i] = *(u32*)&hv;
}

// ---- out init: bpl bias for c1..c3 regions --------------------------------
__global__ void init_out_kernel(const float* __restrict__ bpl1,
                                const float* __restrict__ bpl2,
                                const float* __restrict__ bpl3,
                                float* __restrict__ out) {
    int i = blockIdx.x * blockDim.x + threadIdx.x;
    if (i >= 64 * 224) return;
    int j = i % 224;
    out[(i / 224) * 240 + j] = (j < 128) ? bpl1[0] : (j < 192) ? bpl2[0] : bpl3[0];
}

// ---- conv tile worker ------------------------------------------------------
// 128 threads = 4 warps as 2(m) x 2(n). Warp tile 64o x 32n.
// Block tile: 128 o x 64 n = R(2) rows x TW(32) cols stripe.
// SMEM: sCol(64f)@0, B @1024: [(R+2)*(TW+2) pos][40 f16], XOR swizzle.
template <int H, int W, int TW, int LTW, int R, int BASE>
__device__ void conv_tile_impl(
    int tbid, const float* __restrict__ x, const uint4* __restrict__ wA,
    const float* __restrict__ bs, const float* __restrict__ wt,
    const float* __restrict__ bt, const float* __restrict__ wpl,
    float* __restrict__ out, char* smem) {
    constexpr int NW = TW + 2;
    constexpr int NP = (R + 2) * NW;
    constexpr int B_OFF = 1024;
    constexpr int CT = W / TW;
    constexpr int TW4 = TW / 4;

    float* sCol = (float*)smem;
    const u32 smu = smem_u32(smem);
    const u32 bbase = smu + B_OFF;

    const int tid = threadIdx.x;
    const int warp = tid >> 5;
    const int lane = tid & 31;
    const int warpm = warp & 1;
    const int warpn = warp >> 1;   // 0..1, each 32 n

    const int TPB = (H / R) * CT;
    const int b = tbid / TPB;
    const int rem = tbid - b * TPB;
    const int h0 = (rem / CT) * R;
    const int w0 = (rem - (rem / CT) * CT) * TW;
    const float* xb = x + (size_t)b * 128 * H * W;

    if (tid < R * TW) sCol[tid] = 0.f;

    // hoisted B-tile geometry (2 ldmatrix groups, each 16 n)
    int p0[2];
#pragma unroll
    for (int j = 0; j < 2; j++) {
        int ng = warpn * 32 + j * 16 + (lane >> 4) * 8;
        int trow = ng >> LTW;
        int tcol = ng & (TW - 1);
        p0[j] = trow * NW + tcol + (lane & 7);
    }
    const int kbh = (lane >> 3) & 1;

    float d[4][4][4];
#pragma unroll
    for (int mi = 0; mi < 4; mi++)
#pragma unroll
        for (int nj = 0; nj < 4; nj++)
#pragma unroll
            for (int q = 0; q < 4; q++) d[mi][nj][q] = 0.f;

    for (int cc = 0; cc < 4; cc++) {
        __syncthreads();  // protect prior chunk's readers
        // stage B: 32 channels (16 half2 pairs) x NP positions.
        // cp = tid>>3 (16 groups of 8 threads); float4 interior + scalar halo.
        {
            const int cp = tid >> 3;
            const float* xc0 = xb + (size_t)(cc * 32 + 2 * cp) * H * W;
            // halo columns (w = -1 and w = TW)
            for (int it = tid & 7; it < (R + 2) * 2; it += 8) {
                int r = it >> 1;
                int w = (it & 1) * (NW - 1);
                int gh = h0 + r - 1;
                int gw = w0 + w - 1;
                float v0 = 0.f, v1 = 0.f;
                if (gh >= 0 && gh < H && (unsigned)gw < (unsigned)W) {
                    const float* bp = xc0 + gh * W + gw;
                    v0 = bp[0];
                    v1 = bp[H * W];
                }
                int p = r * NW + w;
                __half2 hv = __floats2half2_rn(v0, v1);
                int word = p * 20 + ((((cp >> 2) ^ (p & 3)) << 2)) + (cp & 3);
                *(__half2*)(smem + B_OFF + word * 4) = hv;
            }
            // interior: float4 loads (4 positions per LDG)
            for (int it = tid & 7; it < (R + 2) * TW4; it += 8) {
                int r = it / TW4;
                int w4 = (it - r * TW4) * 4;
                int gh = h0 + r - 1;
                float4 v0 = {0.f, 0.f, 0.f, 0.f}, v1 = v0;
                if (gh >= 0 && gh < H) {
                    const float* bp = xc0 + gh * W + (w0 + w4);
                    v0 = *(const float4*)bp;
                    v1 = *(const float4*)(bp + H * W);
                }
                const float* f0 = (const float*)&v0;
                const float* f1 = (const float*)&v1;
#pragma unroll
                for (int dw = 0; dw < 4; dw++) {
                    int p = r * NW + w4 + dw + 1;
                    __half2 hv = __floats2half2_rn(f0[dw], f1[dw]);
                    int word = p * 20 + ((((cp >> 2) ^ (p & 3)) << 2)) + (cp & 3);
                    *(__half2*)(smem + B_OFF + word * 4) = hv;
                }
            }
        }
        __syncthreads();

        // 9 taps straight-line: A via LDG.128 (L1-cached), B via ldmatrix
#pragma unroll
        for (int tap = 0; tap < 9; tap++) {
            const int gi = cc * 9 + tap;
            const int dy = tap / 3;
            const int dx = tap - dy * 3;
            const int pofs = dy * NW + dx;
#pragma unroll
            for (int ks = 0; ks < 2; ks++) {
                uint4 a[4];
#pragma unroll
                for (int mi = 0; mi < 4; mi++) {
                    int rg = warpm * 4 + mi;
                    a[mi] = wA[((gi * 8 + rg) * 2 + ks) * 32 + lane];
                }
                const int kb = ks * 2 + kbh;
#pragma unroll
                for (int j = 0; j < 2; j++) {
                    int p = p0[j] + pofs;
                    u32 bf[4];
                    ldm_x4(bf, bbase + p * 80 + ((kb ^ (p & 3)) << 4));
#pragma unroll
                    for (int mi = 0; mi < 4; mi++) {
                        mma16816(d[mi][2 * j], a[mi], bf[0], bf[1]);
                        mma16816(d[mi][2 * j + 1], a[mi], bf[2], bf[3]);
                    }
                }
            }
        }
    }

    // ---- epilogue: bias + ReLU + dot(w_t), reduce, pool -------------------
    const int g = lane >> 2;
    const int tid4 = lane & 3;
    float bsv[4][2], wtv[4][2];
#pragma unroll
    for (int mi = 0; mi < 4; mi++)
#pragma unroll
        for (int hh = 0; hh < 2; hh++) {
            int o = warpm * 64 + mi * 16 + hh * 8 + g;
            bsv[mi][hh] = bs[o];
            wtv[mi][hh] = wt[o];
        }
    __syncthreads();
#pragma unroll
    for (int nj = 0; nj < 4; nj++) {
        float v0 = 0.f, v1 = 0.f;
#pragma unroll
        for (int mi = 0; mi < 4; mi++) {
            v0 += fmaxf(d[mi][nj][0] + bsv[mi][0], 0.f) * wtv[mi][0]
                + fmaxf(d[mi][nj][2] + bsv[mi][1], 0.f) * wtv[mi][1];
            v1 += fmaxf(d[mi][nj][1] + bsv[mi][0], 0.f) * wtv[mi][0]
                + fmaxf(d[mi][nj][3] + bsv[mi][1], 0.f) * wtv[mi][1];
        }
        v0 += __shfl_xor_sync(0xffffffffu, v0, 4);
        v0 += __shfl_xor_sync(0xffffffffu, v0, 8);
        v0 += __shfl_xor_sync(0xffffffffu, v0, 16);
        v1 += __shfl_xor_sync(0xffffffffu, v1, 4);
        v1 += __shfl_xor_sync(0xffffffffu, v1, 8);
        v1 += __shfl_xor_sync(0xffffffffu, v1, 16);
        if (lane < 4) {
            int n = warpn * 32 + nj * 8 + tid4 * 2;
            atomicAdd(&sCol[n], v0);
            atomicAdd(&sCol[n + 1], v1);
        }
    }
    __syncthreads();

    if (tid < TW) {
        const float btv = bt[0];
        float s = 0.f;
#pragma unroll
        for (int r = 0; r < R; r++)
            s += wpl[h0 + r] * (sCol[r * TW + tid] + btv);
        atomicAdd(&out[b * 240 + BASE + w0 + tid], s);
    }
}

// ---- p5 tile: tidy 1x1 (512->1) + pool over h=8, memory bound -------------
// 128 threads: w = tid&15, g = tid>>4 (8 channel groups).
__device__ void p5_tile(int b, const float* __restrict__ p5,
                        const float* __restrict__ wt,
                        const float* __restrict__ bt,
                        const float* __restrict__ wpl,
                        const float* __restrict__ bpl,
                        float* __restrict__ out, char* smem) {
    float* red = (float*)smem;          // 128 floats
    float* spl = (float*)smem + 128;    // 8 floats
    const int tid = threadIdx.x;
    const int w = tid & 15;
    const int g = tid >> 4;
    if (tid < 8) spl[tid] = wpl[tid];
    __syncthreads();

    const float* pb = p5 + (size_t)b * 512 * 8 * 16;
    float accv = 0.f;
    for (int c = g; c < 512; c += 8) {
        float wc = wt[c];
        const float* row = pb + (size_t)c * 8 * 16 + w;
#pragma unroll
        for (int h = 0; h < 8; h++)
            accv = fmaf(wc * spl[h], row[h * 16], accv);
    }
    red[tid] = accv;
    __syncthreads();
    if (tid < 16) {
        float s = 0.f;
#pragma unroll
        for (int gg = 0; gg < 8; gg++) s += red[gg * 16 + tid];
        float sumpl = 0.f;
#pragma unroll
        for (int h = 0; h < 8; h++) sumpl += spl[h];
        out[b * 240 + 224 + tid] = s + bt[0] * sumpl + bpl[0];
    }
}

// ---- fused kernel: all conv levels + p5 in one grid ------------------------
// L1: 64 b x 32 h x 4 w = 8192 | L2: 64 x 16 x 2 = 2048 | L3: 64 x 8 x 1 = 512
// blocks: [0,8192) L1 | [8192,10240) L2 | [10240,10752) L3 | [10752,10816) p5
__global__ void __launch_bounds__(128, 4)
fused_kernel(const float* __restrict__ p2, const float* __restrict__ p3,
             const float* __restrict__ p4, const float* __restrict__ p5,
             const uint4* __restrict__ wA,
             const float* __restrict__ bs1, const float* __restrict__ bs2,
             const float* __restrict__ bs3,
             const float* __restrict__ wt1, const float* __restrict__ bt1,
             const float* __restrict__ wt2, const float* __restrict__ bt2,
             const float* __restrict__ wt3, const float* __restrict__ bt3,
             const float* __restrict__ wt4, const float* __restrict__ bt4,
             const float* __restrict__ wpl1, const float* __restrict__ wpl2,
             const float* __restrict__ wpl3, const float* __restrict__ wpl4,
             const float* __restrict__ bpl4,
             float* __restrict__ out) {
    extern __shared__ char smem[];
    const int bid = blockIdx.x;
    if (bid < 8192) {
        conv_tile_impl<64, 128, 32, 5, 2, 0>(bid, p2, wA, bs1, wt1, bt1,
                                             wpl1, out, smem);
    } else if (bid < 10240) {
        conv_tile_impl<32, 64, 32, 5, 2, 128>(bid - 8192, p3, wA + 36 * 512,
                                              bs2, wt2, bt2, wpl2, out, smem);
    } else if (bid < 10752) {
        conv_tile_impl<16, 32, 32, 5, 2, 192>(bid - 10240, p4, wA + 72 * 512,
                                              bs3, wt3, bt3, wpl3, out, smem);
    } else {
        p5_tile(bid - 10752, p5, wt4, bt4, wpl4, bpl4, out, smem);
    }
}

// ---------------------------------------------------------------------------
extern "C" void kernel_launch(void* const* d_in, const int* in_sizes, int n_in,
                              void* d_out, int out_size) {
    const float* p2 = (const float*)d_in[0];
    const float* p3 = (const float*)d_in[1];
    const float* p4 = (const float*)d_in[2];
    const float* p5 = (const float*)d_in[3];
    const float* w_s1 = (const float*)d_in[4];
    const float* b_s1 = (const float*)d_in[5];
    const float* w_s2 = (const float*)d_in[6];
    const float* b_s2 = (const float*)d_in[7];
    const float* w_s3 = (const float*)d_in[8];
    const float* b_s3 = (const float*)d_in[9];
    const float* w_t1 = (const float*)d_in[10];
    const float* b_t1 = (const float*)d_in[11];
    const float* w_t2 = (const float*)d_in[12];
    const float* b_t2 = (const float*)d_in[13];
    const float* w_t3 = (const float*)d_in[14];
    const float* b_t3 = (const float*)d_in[15];
    const float* w_t4 = (const float*)d_in[16];
    const float* b_t4 = (const float*)d_in[17];
    const float* w_pl1 = (const float*)d_in[18];
    const float* b_pl1 = (const float*)d_in[19];
    const float* w_pl2 = (const float*)d_in[20];
    const float* b_pl2 = (const float*)d_in[21];
    const float* w_pl3 = (const float*)d_in[22];
    const float* b_pl3 = (const float*)d_in[23];
    const float* w_pl4 = (const float*)d_in[24];
    const float* b_pl4 = (const float*)d_in[25];
    float* out = (float*)d_out;

    prep_wA_kernel<<<(3 * 36 * 2048 + 255) / 256, 256>>>(w_s1, w_s2, w_s3);
    init_out_kernel<<<(64 * 224 + 255) / 256, 256>>>(b_pl1, b_pl2, b_pl3, out);

    uint4* wAd;
    cudaGetSymbolAddress((void**)&wAd, g_wA);

    cudaFuncSetAttribute(fused_kernel,
                         cudaFuncAttributeMaxDynamicSharedMemorySize,
                         SMEM_BYTES);
    fused_kernel<<<10816, 128, SMEM_BYTES>>>(
        p2, p3, p4, p5, wAd,
        b_s1, b_s2, b_s3,
        w_t1, b_t1, w_t2, b_t2, w_t3, b_t3, w_t4, b_t4,
        w_pl1, w_pl2, w_pl3, w_pl4, b_pl4, out);
}

// round 13
// speedup vs baseline: 1.3605x; 1.0277x over previous
#include <cuda_runtime.h>
#include <cuda_fp16.h>
#include <cstdint>

// ---------------------------------------------------------------------------
// FPN head via legacy tensor cores (mma.sync m16n8k16 f16, fp32 accum).
// R13: 8 blocks/SM (64 threads = 2 warps, block tile 128o x 32n, ~115 regs,
// 6.8KB smem) -> 8 independent barrier domains/SM (was 4); a barrier now
// idles only 2 warps while 14 keep the tensor pipe fed.
// Fused single launch for all levels + p5. A fragment-direct via LDG.128.
// Output: [64, 240] fp32  (c1:128 | c2:64 | c3:32 | c4:16)
// ---------------------------------------------------------------------------

typedef unsigned int u32;

// A fragment image: [l][gi(36)][rg(8)][ks(2)][lane(32)] x uint4
__device__ uint4 g_wA[3 * 36 * 8 * 2 * 32];

// per-block smem: sCol(32f)/p5 scratch @0, B @1024: (R+2)*(TW+2)*80 bytes
#define SMEM_BYTES 6784    // 1024 + 4*18*80

// ---- PTX helpers ----------------------------------------------------------
__device__ __forceinline__ u32 smem_u32(const void* p) {
    u32 a;
    asm("{ .reg .u64 t; cvta.to.shared.u64 t, %1; cvt.u32.u64 %0, t; }"
        : "=r"(a) : "l"(p));
    return a;
}
__device__ __forceinline__ void ldm_x4(u32* r, u32 addr) {
    asm volatile("ldmatrix.sync.aligned.m8n8.x4.shared.b16 {%0,%1,%2,%3}, [%4];"
                 : "=r"(r[0]), "=r"(r[1]), "=r"(r[2]), "=r"(r[3]) : "r"(addr));
}
__device__ __forceinline__ void mma16816(float* d, const uint4 a, u32 b0, u32 b1) {
    asm volatile(
        "mma.sync.aligned.m16n8k16.row.col.f32.f16.f16.f32 "
        "{%0,%1,%2,%3}, {%4,%5,%6,%7}, {%8,%9}, {%0,%1,%2,%3};"
        : "+f"(d[0]), "+f"(d[1]), "+f"(d[2]), "+f"(d[3])
        : "r"(a.x), "r"(a.y), "r"(a.z), "r"(a.w), "r"(b0), "r"(b1));
}

// ---- weight prep: w[o][c][tap] fp32 -> A fragment image -------------------
__global__ void prep_wA_kernel(const float* __restrict__ w1,
                               const float* __restrict__ w2,
                               const float* __restrict__ w3) {
    int i = blockIdx.x * 256 + threadIdx.x;          // one u32 each
    if (i >= 3 * 36 * 2048) return;
    int q    = i & 3;
    int lane = (i >> 2) & 31;
    int ks   = (i >> 7) & 1;
    int rg   = (i >> 8) & 7;
    int gi   = (i >> 11) % 36;
    int l    = i / (36 << 11);
    const float* src = (l == 0) ? w1 : (l == 1) ? w2 : w3;
    int o = rg * 16 + (lane >> 2) + (q & 1) * 8;
    int k = ks * 16 + (lane & 3) * 2 + (q >> 1) * 8;
    int c = (gi / 9) * 32 + k;
    int tap = gi % 9;
    __half2 hv = __floats2half2_rn(src[o * 1152 + c * 9 + tap],
                                   src[o * 1152 + (c + 1) * 9 + tap]);
    ((u32*)g_wA)[i] = *(u32*)&hv;
}

// ---- out init: bpl bias for c1..c3 regions --------------------------------
__global__ void init_out_kernel(const float* __restrict__ bpl1,
                                const float* __restrict__ bpl2,
                                const float* __restrict__ bpl3,
                                float* __restrict__ out) {
    int i = blockIdx.x * blockDim.x + threadIdx.x;
    if (i >= 64 * 224) return;
    int j = i % 224;
    out[(i / 224) * 240 + j] = (j < 128) ? bpl1[0] : (j < 192) ? bpl2[0] : bpl3[0];
}

// ---- conv tile worker ------------------------------------------------------
// 64 threads = 2 warps (warpm 0/1, each 64o x 32n). Block tile 128o x 32n =
// R(2) rows x TW(16) cols stripe.
// SMEM: sCol(32f)@0, B @1024: [(R+2)*(TW+2) pos][40 f16], XOR swizzle.
template <int H, int W, int BASE>
__device__ void conv_tile_impl(
    int tbid, const float* __restrict__ x, const uint4* __restrict__ wA,
    const float* __restrict__ bs, const float* __restrict__ wt,
    const float* __restrict__ bt, const float* __restrict__ wpl,
    float* __restrict__ out, char* smem) {
    constexpr int TW = 16;
    constexpr int R = 2;
    constexpr int NW = TW + 2;
    constexpr int NP = (R + 2) * NW;   // 72
    constexpr int B_OFF = 1024;
    constexpr int CT = W / TW;
    constexpr int TW4 = TW / 4;

    float* sCol = (float*)smem;
    const u32 smu = smem_u32(smem);
    const u32 bbase = smu + B_OFF;

    const int tid = threadIdx.x;
    const int warpm = tid >> 5;        // 0..1
    const int lane = tid & 31;

    const int TPB = (H / R) * CT;
    const int b = tbid / TPB;
    const int rem = tbid - b * TPB;
    const int h0 = (rem / CT) * R;
    const int w0 = (rem - (rem / CT) * CT) * TW;
    const float* xb = x + (size_t)b * 128 * H * W;

    if (tid < R * TW) sCol[tid] = 0.f;

    // hoisted B-tile geometry (2 ldmatrix groups, each 16 n)
    int p0[2];
#pragma unroll
    for (int j = 0; j < 2; j++) {
        int ng = j * 16 + (lane >> 4) * 8;   // 0,8,16,24
        int trow = ng >> 4;                  // row within R
        int tcol = ng & (TW - 1);
        p0[j] = trow * NW + tcol + (lane & 7);
    }
    const int kbh = (lane >> 3) & 1;

    float d[4][4][4];
#pragma unroll
    for (int mi = 0; mi < 4; mi++)
#pragma unroll
        for (int nj = 0; nj < 4; nj++)
#pragma unroll
            for (int q = 0; q < 4; q++) d[mi][nj][q] = 0.f;

    for (int cc = 0; cc < 4; cc++) {
        __syncthreads();  // protect prior chunk's readers
        // stage B: 32 channels (16 half2 pairs) x NP positions.
        // cp = tid>>2 (16 groups of 4 threads); float4 interior + scalar halo.
        {
            const int cp = tid >> 2;
            const float* xc0 = xb + (size_t)(cc * 32 + 2 * cp) * H * W;
            // halo columns (w = -1 and w = TW)
            for (int it = tid & 3; it < (R + 2) * 2; it += 4) {
                int r = it >> 1;
                int w = (it & 1) * (NW - 1);
                int gh = h0 + r - 1;
                int gw = w0 + w - 1;
                float v0 = 0.f, v1 = 0.f;
                if (gh >= 0 && gh < H && (unsigned)gw < (unsigned)W) {
                    const float* bp = xc0 + gh * W + gw;
                    v0 = bp[0];
                    v1 = bp[H * W];
                }
                int p = r * NW + w;
                __half2 hv = __floats2half2_rn(v0, v1);
                int word = p * 20 + ((((cp >> 2) ^ (p & 3)) << 2)) + (cp & 3);
                *(__half2*)(smem + B_OFF + word * 4) = hv;
            }
            // interior: float4 loads (4 positions per LDG)
            for (int it = tid & 3; it < (R + 2) * TW4; it += 4) {
                int r = it / TW4;
                int w4 = (it - r * TW4) * 4;
                int gh = h0 + r - 1;
                float4 v0 = {0.f, 0.f, 0.f, 0.f}, v1 = v0;
                if (gh >= 0 && gh < H) {
                    const float* bp = xc0 + gh * W + (w0 + w4);
                    v0 = *(const float4*)bp;
                    v1 = *(const float4*)(bp + H * W);
                }
                const float* f0 = (const float*)&v0;
                const float* f1 = (const float*)&v1;
#pragma unroll
                for (int dw = 0; dw < 4; dw++) {
                    int p = r * NW + w4 + dw + 1;
                    __half2 hv = __floats2half2_rn(f0[dw], f1[dw]);
                    int word = p * 20 + ((((cp >> 2) ^ (p & 3)) << 2)) + (cp & 3);
                    *(__half2*)(smem + B_OFF + word * 4) = hv;
                }
            }
        }
        __syncthreads();

        // 9 taps straight-line: A via LDG.128 (L1-cached), B via ldmatrix
#pragma unroll
        for (int tap = 0; tap < 9; tap++) {
            const int gi = cc * 9 + tap;
            const int dy = tap / 3;
            const int dx = tap - dy * 3;
            const int pofs = dy * NW + dx;
#pragma unroll
            for (int ks = 0; ks < 2; ks++) {
                uint4 a[4];
#pragma unroll
                for (int mi = 0; mi < 4; mi++) {
                    int rg = warpm * 4 + mi;
                    a[mi] = wA[((gi * 8 + rg) * 2 + ks) * 32 + lane];
                }
                const int kb = ks * 2 + kbh;
#pragma unroll
                for (int j = 0; j < 2; j++) {
                    int p = p0[j] + pofs;
                    u32 bf[4];
                    ldm_x4(bf, bbase + p * 80 + ((kb ^ (p & 3)) << 4));
#pragma unroll
                    for (int mi = 0; mi < 4; mi++) {
                        mma16816(d[mi][2 * j], a[mi], bf[0], bf[1]);
                        mma16816(d[mi][2 * j + 1], a[mi], bf[2], bf[3]);
                    }
                }
            }
        }
    }

    // ---- epilogue: bias + ReLU + dot(w_t), reduce, pool -------------------
    const int g = lane >> 2;
    const int tid4 = lane & 3;
    float bsv[4][2], wtv[4][2];
#pragma unroll
    for (int mi = 0; mi < 4; mi++)
#pragma unroll
        for (int hh = 0; hh < 2; hh++) {
            int o = warpm * 64 + mi * 16 + hh * 8 + g;
            bsv[mi][hh] = bs[o];
            wtv[mi][hh] = wt[o];
        }
    __syncthreads();
#pragma unroll
    for (int nj = 0; nj < 4; nj++) {
        float v0 = 0.f, v1 = 0.f;
#pragma unroll
        for (int mi = 0; mi < 4; mi++) {
            v0 += fmaxf(d[mi][nj][0] + bsv[mi][0], 0.f) * wtv[mi][0]
                + fmaxf(d[mi][nj][2] + bsv[mi][1], 0.f) * wtv[mi][1];
            v1 += fmaxf(d[mi][nj][1] + bsv[mi][0], 0.f) * wtv[mi][0]
                + fmaxf(d[mi][nj][3] + bsv[mi][1], 0.f) * wtv[mi][1];
        }
        v0 += __shfl_xor_sync(0xffffffffu, v0, 4);
        v0 += __shfl_xor_sync(0xffffffffu, v0, 8);
        v0 += __shfl_xor_sync(0xffffffffu, v0, 16);
        v1 += __shfl_xor_sync(0xffffffffu, v1, 4);
        v1 += __shfl_xor_sync(0xffffffffu, v1, 8);
        v1 += __shfl_xor_sync(0xffffffffu, v1, 16);
        if (lane < 4) {
            int n = nj * 8 + tid4 * 2;
            atomicAdd(&sCol[n], v0);
            atomicAdd(&sCol[n + 1], v1);
        }
    }
    __syncthreads();

    if (tid < TW) {
        const float btv = bt[0];
        float s = 0.f;
#pragma unroll
        for (int r = 0; r < R; r++)
            s += wpl[h0 + r] * (sCol[r * TW + tid] + btv);
        atomicAdd(&out[b * 240 + BASE + w0 + tid], s);
    }
}

// ---- p5 tile: tidy 1x1 (512->1) + pool over h=8, memory bound -------------
// 64 threads: w = tid&15, g = tid>>4 (4 channel groups).
__device__ void p5_tile(int b, const float* __restrict__ p5,
                        const float* __restrict__ wt,
                        const float* __restrict__ bt,
                        const float* __restrict__ wpl,
                        const float* __restrict__ bpl,
                        float* __restrict__ out, char* smem) {
    float* red = (float*)smem;          // 64 floats
    float* spl = (float*)smem + 64;     // 8 floats
    const int tid = threadIdx.x;
    const int w = tid & 15;
    const int g = tid >> 4;
    if (tid < 8) spl[tid] = wpl[tid];
    __syncthreads();

    const float* pb = p5 + (size_t)b * 512 * 8 * 16;
    float accv = 0.f;
    for (int c = g; c < 512; c += 4) {
        float wc = wt[c];
        const float* row = pb + (size_t)c * 8 * 16 + w;
#pragma unroll
        for (int h = 0; h < 8; h++)
            accv = fmaf(wc * spl[h], row[h * 16], accv);
    }
    red[tid] = accv;
    __syncthreads();
    if (tid < 16) {
        float s = 0.f;
#pragma unroll
        for (int gg = 0; gg < 4; gg++) s += red[gg * 16 + tid];
        float sumpl = 0.f;
#pragma unroll
        for (int h = 0; h < 8; h++) sumpl += spl[h];
        out[b * 240 + 224 + tid] = s + bt[0] * sumpl + bpl[0];
    }
}

// ---- fused kernel: all conv levels + p5 in one grid ------------------------
// Tiles (R=2, TW=16): L1 64x(32x8)=16384 | L2 64x(16x4)=4096 | L3 64x(8x2)=1024
// blocks: [0,16384) L1 | [16384,20480) L2 | [20480,21504) L3 | [21504,21568) p5
__global__ void __launch_bounds__(64, 8)
fused_kernel(const float* __restrict__ p2, const float* __restrict__ p3,
             const float* __restrict__ p4, const float* __restrict__ p5,
             const uint4* __restrict__ wA,
             const float* __restrict__ bs1, const float* __restrict__ bs2,
             const float* __restrict__ bs3,
             const float* __restrict__ wt1, const float* __restrict__ bt1,
             const float* __restrict__ wt2, const float* __restrict__ bt2,
             const float* __restrict__ wt3, const float* __restrict__ bt3,
             const float* __restrict__ wt4, const float* __restrict__ bt4,
             const float* __restrict__ wpl1, const float* __restrict__ wpl2,
             const float* __restrict__ wpl3, const float* __restrict__ wpl4,
             const float* __restrict__ bpl4,
             float* __restrict__ out) {
    extern __shared__ char smem[];
    const int bid = blockIdx.x;
    if (bid < 16384) {
        conv_tile_impl<64, 128, 0>(bid, p2, wA, bs1, wt1, bt1, wpl1, out, smem);
    } else if (bid < 20480) {
        conv_tile_impl<32, 64, 128>(bid - 16384, p3, wA + 36 * 512,
                                    bs2, wt2, bt2, wpl2, out, smem);
    } else if (bid < 21504) {
        conv_tile_impl<16, 32, 192>(bid - 20480, p4, wA + 72 * 512,
                                    bs3, wt3, bt3, wpl3, out, smem);
    } else {
        p5_tile(bid - 21504, p5, wt4, bt4, wpl4, bpl4, out, smem);
    }
}

// ---------------------------------------------------------------------------
extern "C" void kernel_launch(void* const* d_in, const int* in_sizes, int n_in,
                              void* d_out, int out_size) {
    const float* p2 = (const float*)d_in[0];
    const float* p3 = (const float*)d_in[1];
    const float* p4 = (const float*)d_in[2];
    const float* p5 = (const float*)d_in[3];
    const float* w_s1 = (const float*)d_in[4];
    const float* b_s1 = (const float*)d_in[5];
    const float* w_s2 = (const float*)d_in[6];
    const float* b_s2 = (const float*)d_in[7];
    const float* w_s3 = (const float*)d_in[8];
    const float* b_s3 = (const float*)d_in[9];
    const float* w_t1 = (const float*)d_in[10];
    const float* b_t1 = (const float*)d_in[11];
    const float* w_t2 = (const float*)d_in[12];
    const float* b_t2 = (const float*)d_in[13];
    const float* w_t3 = (const float*)d_in[14];
    const float* b_t3 = (const float*)d_in[15];
    const float* w_t4 = (const float*)d_in[16];
    const float* b_t4 = (const float*)d_in[17];
    const float* w_pl1 = (const float*)d_in[18];
    const float* b_pl1 = (const float*)d_in[19];
    const float* w_pl2 = (const float*)d_in[20];
    const float* b_pl2 = (const float*)d_in[21];
    const float* w_pl3 = (const float*)d_in[22];
    const float* b_pl3 = (const float*)d_in[23];
    const float* w_pl4 = (const float*)d_in[24];
    const float* b_pl4 = (const float*)d_in[25];
    float* out = (float*)d_out;

    prep_wA_kernel<<<(3 * 36 * 2048 + 255) / 256, 256>>>(w_s1, w_s2, w_s3);
    init_out_kernel<<<(64 * 224 + 255) / 256, 256>>>(b_pl1, b_pl2, b_pl3, out);

    uint4* wAd;
    cudaGetSymbolAddress((void**)&wAd, g_wA);

    cudaFuncSetAttribute(fused_kernel,
                         cudaFuncAttributeMaxDynamicSharedMemorySize,
                         SMEM_BYTES);
    fused_kernel<<<21568, 64, SMEM_BYTES>>>(
        p2, p3, p4, p5, wAd,
        b_s1, b_s2, b_s3,
        w_t1, b_t1, w_t2, b_t2, w_t3, b_t3, w_t4, b_t4,
        w_pl1, w_pl2, w_pl3, w_pl4, b_pl4, out);
}

// round 14
// speedup vs baseline: 1.4116x; 1.0376x over previous
#include <cuda_runtime.h>
#include <cuda_fp16.h>
#include <cstdint>

// ---------------------------------------------------------------------------
// FPN head via legacy tensor cores (mma.sync m16n8k16 f16, fp32 accum).
// R14: single-phase B staging (all 128 channels at once, 18KB/block) ->
// ONE barrier before a fully sync-free 72-step MMA stream (was 4 stage/
// barrier cycles). B layout [pos][128ch], 16B-block swizzle kb^(p&7) keeps
// ldmatrix conflict-free. Still 8 blocks/SM (64 thr), fused single launch.
// Output: [64, 240] fp32  (c1:128 | c2:64 | c3:32 | c4:16)
// ---------------------------------------------------------------------------

typedef unsigned int u32;

// A fragment image: [l][gi(36)][rg(8)][ks(2)][lane(32)] x uint4
__device__ uint4 g_wA[3 * 36 * 8 * 2 * 32];

// per-block smem: sCol(32f)/p5 scratch @0, B @1024: 72 pos x 256 B
#define SMEM_BYTES 19456   // 1024 + 72*256

// ---- PTX helpers ----------------------------------------------------------
__device__ __forceinline__ u32 smem_u32(const void* p) {
    u32 a;
    asm("{ .reg .u64 t; cvta.to.shared.u64 t, %1; cvt.u32.u64 %0, t; }"
        : "=r"(a) : "l"(p));
    return a;
}
__device__ __forceinline__ void ldm_x4(u32* r, u32 addr) {
    asm volatile("ldmatrix.sync.aligned.m8n8.x4.shared.b16 {%0,%1,%2,%3}, [%4];"
                 : "=r"(r[0]), "=r"(r[1]), "=r"(r[2]), "=r"(r[3]) : "r"(addr));
}
__device__ __forceinline__ void mma16816(float* d, const uint4 a, u32 b0, u32 b1) {
    asm volatile(
        "mma.sync.aligned.m16n8k16.row.col.f32.f16.f16.f32 "
        "{%0,%1,%2,%3}, {%4,%5,%6,%7}, {%8,%9}, {%0,%1,%2,%3};"
        : "+f"(d[0]), "+f"(d[1]), "+f"(d[2]), "+f"(d[3])
        : "r"(a.x), "r"(a.y), "r"(a.z), "r"(a.w), "r"(b0), "r"(b1));
}

// ---- weight prep + out init fused -----------------------------------------
// items [0, 221184): weight u32s ; items [221184, 235520): out init
__global__ void prep_kernel(const float* __restrict__ w1,
                            const float* __restrict__ w2,
                            const float* __restrict__ w3,
                            const float* __restrict__ bpl1,
                            const float* __restrict__ bpl2,
                            const float* __restrict__ bpl3,
                            float* __restrict__ out) {
    int i = blockIdx.x * 256 + threadIdx.x;
    if (i < 3 * 36 * 2048) {
        int q    = i & 3;
        int lane = (i >> 2) & 31;
        int ks   = (i >> 7) & 1;
        int rg   = (i >> 8) & 7;
        int gi   = (i >> 11) % 36;
        int l    = i / (36 << 11);
        const float* src = (l == 0) ? w1 : (l == 1) ? w2 : w3;
        int o = rg * 16 + (lane >> 2) + (q & 1) * 8;
        int k = ks * 16 + (lane & 3) * 2 + (q >> 1) * 8;
        int c = (gi / 9) * 32 + k;
        int tap = gi % 9;
        __half2 hv = __floats2half2_rn(src[o * 1152 + c * 9 + tap],
                                       src[o * 1152 + (c + 1) * 9 + tap]);
        ((u32*)g_wA)[i] = *(u32*)&hv;
    } else {
        int j2 = i - 3 * 36 * 2048;
        if (j2 >= 64 * 224) return;
        int j = j2 % 224;
        out[(j2 / 224) * 240 + j] =
            (j < 128) ? bpl1[0] : (j < 192) ? bpl2[0] : bpl3[0];
    }
}

// ---- conv tile worker ------------------------------------------------------
// 64 threads = 2 warps (warpm 0/1, each 64o x 32n). Block tile 128o x 32n =
// R(2) rows x TW(16) cols stripe.
// SMEM: sCol(32f)@0, B @1024: [(R+2)*(TW+2)=72 pos][128 f16 = 256 B],
//   16B-block swizzle: block kb at position p stored at slot kb ^ (p & 7).
template <int H, int W, int BASE>
__device__ void conv_tile_impl(
    int tbid, const float* __restrict__ x, const uint4* __restrict__ wA,
    const float* __restrict__ bs, const float* __restrict__ wt,
    const float* __restrict__ bt, const float* __restrict__ wpl,
    float* __restrict__ out, char* smem) {
    constexpr int TW = 16;
    constexpr int R = 2;
    constexpr int NW = TW + 2;
    constexpr int B_OFF = 1024;
    constexpr int CT = W / TW;
    constexpr int TW4 = TW / 4;

    float* sCol = (float*)smem;
    const u32 smu = smem_u32(smem);
    const u32 bbase = smu + B_OFF;

    const int tid = threadIdx.x;
    const int warpm = tid >> 5;        // 0..1
    const int lane = tid & 31;

    const int TPB = (H / R) * CT;
    const int b = tbid / TPB;
    const int rem = tbid - b * TPB;
    const int h0 = (rem / CT) * R;
    const int w0 = (rem - (rem / CT) * CT) * TW;
    const float* xb = x + (size_t)b * 128 * H * W;

    if (tid < R * TW) sCol[tid] = 0.f;

    // hoisted B-tile geometry (2 ldmatrix groups, each 16 n)
    int p0[2];
#pragma unroll
    for (int j = 0; j < 2; j++) {
        int ng = j * 16 + (lane >> 4) * 8;   // 0,8,16,24
        int trow = ng >> 4;                  // row within R
        int tcol = ng & (TW - 1);
        p0[j] = trow * NW + tcol + (lane & 7);
    }
    const int kbh = (lane >> 3) & 1;

    float d[4][4][4];
#pragma unroll
    for (int mi = 0; mi < 4; mi++)
#pragma unroll
        for (int nj = 0; nj < 4; nj++)
#pragma unroll
            for (int q = 0; q < 4; q++) d[mi][nj][q] = 0.f;

    // ---- single-phase staging: all 128 channels ---------------------------
    // 64 half2-pairs per position; cpr rounds of 16 pairs (cp = tid>>2 + 16r)
    {
#pragma unroll 1
        for (int cpr = 0; cpr < 4; cpr++) {
            const int cp = (tid >> 2) + cpr * 16;     // half2 pair 0..63
            const int kb = cp >> 2;                   // 16B block 0..15
            const int cw = cp & 3;                    // u32 within block
            const float* xc0 = xb + (size_t)(2 * cp) * H * W;
            // halo columns (w = -1 and w = TW)
            for (int it = tid & 3; it < (R + 2) * 2; it += 4) {
                int r = it >> 1;
                int w = (it & 1) * (NW - 1);
                int gh = h0 + r - 1;
                int gw = w0 + w - 1;
                float v0 = 0.f, v1 = 0.f;
                if (gh >= 0 && gh < H && (unsigned)gw < (unsigned)W) {
                    const float* bp = xc0 + gh * W + gw;
                    v0 = bp[0];
                    v1 = bp[H * W];
                }
                int p = r * NW + w;
                __half2 hv = __floats2half2_rn(v0, v1);
                int word = p * 64 + ((kb ^ (p & 7)) << 2) + cw;
                *(__half2*)(smem + B_OFF + word * 4) = hv;
            }
            // interior: float4 loads (4 positions per LDG)
            for (int it = tid & 3; it < (R + 2) * TW4; it += 4) {
                int r = it / TW4;
                int w4 = (it - r * TW4) * 4;
                int gh = h0 + r - 1;
                float4 v0 = {0.f, 0.f, 0.f, 0.f}, v1 = v0;
                if (gh >= 0 && gh < H) {
                    const float* bp = xc0 + gh * W + (w0 + w4);
                    v0 = *(const float4*)bp;
                    v1 = *(const float4*)(bp + H * W);
                }
                const float* f0 = (const float*)&v0;
                const float* f1 = (const float*)&v1;
#pragma unroll
                for (int dw = 0; dw < 4; dw++) {
                    int p = r * NW + w4 + dw + 1;
                    __half2 hv = __floats2half2_rn(f0[dw], f1[dw]);
                    int word = p * 64 + ((kb ^ (p & 7)) << 2) + cw;
                    *(__half2*)(smem + B_OFF + word * 4) = hv;
                }
            }
        }
    }
    __syncthreads();   // the ONLY pre-MMA barrier

    // ---- sync-free MMA stream: 4 cc (rolled) x 9 taps x 2 ks --------------
#pragma unroll 1
    for (int cc = 0; cc < 4; cc++) {
#pragma unroll
        for (int tap = 0; tap < 9; tap++) {
            const int gi = cc * 9 + tap;
            const int dy = tap / 3;
            const int dx = tap - dy * 3;
            const int pofs = dy * NW + dx;
#pragma unroll
            for (int ks = 0; ks < 2; ks++) {
                uint4 a[4];
#pragma unroll
                for (int mi = 0; mi < 4; mi++) {
                    int rg = warpm * 4 + mi;
                    a[mi] = wA[((gi * 8 + rg) * 2 + ks) * 32 + lane];
                }
                const int kb = cc * 4 + ks * 2 + kbh;   // 0..15
#pragma unroll
                for (int j = 0; j < 2; j++) {
                    int p = p0[j] + pofs;
                    u32 bf[4];
                    ldm_x4(bf, bbase + p * 256 + ((kb ^ (p & 7)) << 4));
#pragma unroll
                    for (int mi = 0; mi < 4; mi++) {
                        mma16816(d[mi][2 * j], a[mi], bf[0], bf[1]);
                        mma16816(d[mi][2 * j + 1], a[mi], bf[2], bf[3]);
                    }
                }
            }
        }
    }

    // ---- epilogue: bias + ReLU + dot(w_t), reduce, pool -------------------
    const int g = lane >> 2;
    const int tid4 = lane & 3;
    float bsv[4][2], wtv[4][2];
#pragma unroll
    for (int mi = 0; mi < 4; mi++)
#pragma unroll
        for (int hh = 0; hh < 2; hh++) {
            int o = warpm * 64 + mi * 16 + hh * 8 + g;
            bsv[mi][hh] = bs[o];
            wtv[mi][hh] = wt[o];
        }
    __syncthreads();
#pragma unroll
    for (int nj = 0; nj < 4; nj++) {
        float v0 = 0.f, v1 = 0.f;
#pragma unroll
        for (int mi = 0; mi < 4; mi++) {
            v0 += fmaxf(d[mi][nj][0] + bsv[mi][0], 0.f) * wtv[mi][0]
                + fmaxf(d[mi][nj][2] + bsv[mi][1], 0.f) * wtv[mi][1];
            v1 += fmaxf(d[mi][nj][1] + bsv[mi][0], 0.f) * wtv[mi][0]
                + fmaxf(d[mi][nj][3] + bsv[mi][1], 0.f) * wtv[mi][1];
        }
        v0 += __shfl_xor_sync(0xffffffffu, v0, 4);
        v0 += __shfl_xor_sync(0xffffffffu, v0, 8);
        v0 += __shfl_xor_sync(0xffffffffu, v0, 16);
        v1 += __shfl_xor_sync(0xffffffffu, v1, 4);
        v1 += __shfl_xor_sync(0xffffffffu, v1, 8);
        v1 += __shfl_xor_sync(0xffffffffu, v1, 16);
        if (lane < 4) {
            int n = nj * 8 + tid4 * 2;
            atomicAdd(&sCol[n], v0);
            atomicAdd(&sCol[n + 1], v1);
        }
    }
    __syncthreads();

    if (tid < TW) {
        const float btv = bt[0];
        float s = 0.f;
#pragma unroll
        for (int r = 0; r < R; r++)
            s += wpl[h0 + r] * (sCol[r * TW + tid] + btv);
        atomicAdd(&out[b * 240 + BASE + w0 + tid], s);
    }
}

// ---- p5 tile: tidy 1x1 (512->1) + pool over h=8, memory bound -------------
// 64 threads: w = tid&15, g = tid>>4 (4 channel groups).
__device__ void p5_tile(int b, const float* __restrict__ p5,
                        const float* __restrict__ wt,
                        const float* __restrict__ bt,
                        const float* __restrict__ wpl,
                        const float* __restrict__ bpl,
                        float* __restrict__ out, char* smem) {
    float* red = (float*)smem;          // 64 floats
    float* spl = (float*)smem + 64;     // 8 floats
    const int tid = threadIdx.x;
    const int w = tid & 15;
    const int g = tid >> 4;
    if (tid < 8) spl[tid] = wpl[tid];
    __syncthreads();

    const float* pb = p5 + (size_t)b * 512 * 8 * 16;
    float accv = 0.f;
    for (int c = g; c < 512; c += 4) {
        float wc = wt[c];
        const float* row = pb + (size_t)c * 8 * 16 + w;
#pragma unroll
        for (int h = 0; h < 8; h++)
            accv = fmaf(wc * spl[h], row[h * 16], accv);
    }
    red[tid] = accv;
    __syncthreads();
    if (tid < 16) {
        float s = 0.f;
#pragma unroll
        for (int gg = 0; gg < 4; gg++) s += red[gg * 16 + tid];
        float sumpl = 0.f;
#pragma unroll
        for (int h = 0; h < 8; h++) sumpl += spl[h];
        out[b * 240 + 224 + tid] = s + bt[0] * sumpl + bpl[0];
    }
}

// ---- fused kernel: all conv levels + p5 in one grid ------------------------
// Tiles (R=2, TW=16): L1 64x(32x8)=16384 | L2 64x(16x4)=4096 | L3 64x(8x2)=1024
// blocks: [0,16384) L1 | [16384,20480) L2 | [20480,21504) L3 | [21504,21568) p5
__global__ void __launch_bounds__(64, 8)
fused_kernel(const float* __restrict__ p2, const float* __restrict__ p3,
             const float* __restrict__ p4, const float* __restrict__ p5,
             const uint4* __restrict__ wA,
             const float* __restrict__ bs1, const float* __restrict__ bs2,
             const float* __restrict__ bs3,
             const float* __restrict__ wt1, const float* __restrict__ bt1,
             const float* __restrict__ wt2, const float* __restrict__ bt2,
             const float* __restrict__ wt3, const float* __restrict__ bt3,
             const float* __restrict__ wt4, const float* __restrict__ bt4,
             const float* __restrict__ wpl1, const float* __restrict__ wpl2,
             const float* __restrict__ wpl3, const float* __restrict__ wpl4,
             const float* __restrict__ bpl4,
             float* __restrict__ out) {
    extern __shared__ char smem[];
    const int bid = blockIdx.x;
    if (bid < 16384) {
        conv_tile_impl<64, 128, 0>(bid, p2, wA, bs1, wt1, bt1, wpl1, out, smem);
    } else if (bid < 20480) {
        conv_tile_impl<32, 64, 128>(bid - 16384, p3, wA + 36 * 512,
                                    bs2, wt2, bt2, wpl2, out, smem);
    } else if (bid < 21504) {
        conv_tile_impl<16, 32, 192>(bid - 20480, p4, wA + 72 * 512,
                                    bs3, wt3, bt3, wpl3, out, smem);
    } else {
        p5_tile(bid - 21504, p5, wt4, bt4, wpl4, bpl4, out, smem);
    }
}

// ---------------------------------------------------------------------------
extern "C" void kernel_launch(void* const* d_in, const int* in_sizes, int n_in,
                              void* d_out, int out_size) {
    const float* p2 = (const float*)d_in[0];
    const float* p3 = (const float*)d_in[1];
    const float* p4 = (const float*)d_in[2];
    const float* p5 = (const float*)d_in[3];
    const float* w_s1 = (const float*)d_in[4];
    const float* b_s1 = (const float*)d_in[5];
    const float* w_s2 = (const float*)d_in[6];
    const float* b_s2 = (const float*)d_in[7];
    const float* w_s3 = (const float*)d_in[8];
    const float* b_s3 = (const float*)d_in[9];
    const float* w_t1 = (const float*)d_in[10];
    const float* b_t1 = (const float*)d_in[11];
    const float* w_t2 = (const float*)d_in[12];
    const float* b_t2 = (const float*)d_in[13];
    const float* w_t3 = (const float*)d_in[14];
    const float* b_t3 = (const float*)d_in[15];
    const float* w_t4 = (const float*)d_in[16];
    const float* b_t4 = (const float*)d_in[17];
    const float* w_pl1 = (const float*)d_in[18];
    const float* b_pl1 = (const float*)d_in[19];
    const float* w_pl2 = (const float*)d_in[20];
    const float* b_pl2 = (const float*)d_in[21];
    const float* w_pl3 = (const float*)d_in[22];
    const float* b_pl3 = (const float*)d_in[23];
    const float* w_pl4 = (const float*)d_in[24];
    const float* b_pl4 = (const float*)d_in[25];
    float* out = (float*)d_out;

    // weights prep + out init in one launch
    prep_kernel<<<(3 * 36 * 2048 + 64 * 224 + 255) / 256, 256>>>(
        w_s1, w_s2, w_s3, b_pl1, b_pl2, b_pl3, out);

    uint4* wAd;
    cudaGetSymbolAddress((void**)&wAd, g_wA);

    cudaFuncSetAttribute(fused_kernel,
                         cudaFuncAttributeMaxDynamicSharedMemorySize,
                         SMEM_BYTES);
    fused_kernel<<<21568, 64, SMEM_BYTES>>>(
        p2, p3, p4, p5, wAd,
        b_s1, b_s2, b_s3,
        w_t1, b_t1, w_t2, b_t2, w_t3, b_t3, w_t4, b_t4,
        w_pl1, w_pl2, w_pl3, w_pl4, b_pl4, out);
}